// round 8
// baseline (speedup 1.0000x reference)
#include <cuda_runtime.h>
#include <cuda_bf16.h>
#include <cstdint>

typedef __nv_bfloat16 bf16;

#define BB 4
#define CC 1024
#define CIN 512
#define NT 2048

// ---------------- static scratch ----------------
__device__ __align__(256) bf16 s_xT_h[BB * NT * CC];
__device__ __align__(256) bf16 s_xT_l[BB * NT * CC];
__device__ __align__(256) bf16 s_wg_h[CIN * CC], s_wg_l[CIN * CC];
__device__ __align__(256) bf16 s_wt_h[CIN * CC], s_wt_l[CIN * CC];
__device__ __align__(256) bf16 s_wp_h[CIN * CC], s_wp_l[CIN * CC];
__device__ __align__(256) bf16 s_ww_h[CC * CIN], s_ww_l[CC * CIN];
__device__ __align__(256) bf16 s_th_h[BB * NT * CIN], s_th_l[BB * NT * CIN];
__device__ __align__(256) bf16 s_ph_h[BB * NT * CIN], s_ph_l[BB * NT * CIN];
__device__ __align__(256) bf16 s_gs_h[BB * CIN * NT], s_gs_l[BB * CIN * NT];
__device__ __align__(256) float s_f[BB * NT * NT];
__device__ __align__(256) bf16 s_at_h[BB * NT * NT], s_at_l[BB * NT * NT];
__device__ __align__(256) bf16 s_y_h[BB * NT * CIN], s_y_l[BB * NT * CIN];
__device__ __align__(256) float s_wy[BB * CC * NT];

// ---------------- helpers ----------------
__device__ __forceinline__ uint32_t smem_u32(const void* p) {
    uint32_t a;
    asm("{ .reg .u64 t; cvta.to.shared.u64 t, %1; cvt.u32.u64 %0, t; }" : "=r"(a) : "l"(p));
    return a;
}
__device__ __forceinline__ void st_split2(bf16* hi, bf16* lo, float v0, float v1) {
    bf16 h0 = __float2bfloat16(v0), h1 = __float2bfloat16(v1);
    *(uint32_t*)hi = (uint32_t)__bfloat16_as_ushort(h0) |
                     ((uint32_t)__bfloat16_as_ushort(h1) << 16);
    bf16 l0 = __float2bfloat16(v0 - __bfloat162float(h0));
    bf16 l1 = __float2bfloat16(v1 - __bfloat162float(h1));
    *(uint32_t*)lo = (uint32_t)__bfloat16_as_ushort(l0) |
                     ((uint32_t)__bfloat16_as_ushort(l1) << 16);
}
__device__ __forceinline__ void st_split4(bf16* hi, bf16* lo, float v0, float v1, float v2, float v3) {
    st_split2(hi, lo, v0, v1);
    st_split2(hi + 2, lo + 2, v2, v3);
}

// ---------------- HMMA GEMM ----------------
// D[r,c] = sum_k (Ah+Al)[r,k] * (Bh+Bl)[c,k]  via HH + HL + LH
// CTA tile 128x256, 8 warps (2x4), warp tile 64x64, K-chunk 32, 3-stage cp.async.
// Smem traffic: 6 MMA per LDSM.x4 (2x better than 32x32 warp tiles).
#define NSTG 3
#define A_TILE_B 8192             // 128 x 32 bf16
#define B_TILE_B 16384            // 256 x 32 bf16
#define STG_BYTES (2 * A_TILE_B + 2 * B_TILE_B)   // Ah, Al, Bh, Bl = 48 KB
#define SMEM_TOTAL (NSTG * STG_BYTES)

// swizzled byte offset of 16B vector (row, kv) in an Nx32 bf16 tile (64B rows)
__device__ __forceinline__ uint32_t sw_off(int row, int kv) {
    return (uint32_t)(row * 64 + ((kv ^ ((row >> 1) & 3)) << 4));
}

__device__ __forceinline__ void cpa_A(uint32_t sdst, const bf16* __restrict__ g,
                                      int ld, int k0, int tid) {
#pragma unroll
    for (int i = 0; i < 2; i++) {
        int idx = tid + i * 256;       // 0..511
        int row = idx >> 2;            // 0..127
        int kv  = idx & 3;
        uint32_t dst = sdst + sw_off(row, kv);
        const void* src = g + (long)row * ld + k0 + kv * 8;
        asm volatile("cp.async.cg.shared.global [%0], [%1], 16;" :: "r"(dst), "l"(src));
    }
}
__device__ __forceinline__ void cpa_B(uint32_t sdst, const bf16* __restrict__ g,
                                      int ld, int k0, int tid) {
#pragma unroll
    for (int i = 0; i < 4; i++) {
        int idx = tid + i * 256;       // 0..1023
        int row = idx >> 2;            // 0..255
        int kv  = idx & 3;
        uint32_t dst = sdst + sw_off(row, kv);
        const void* src = g + (long)row * ld + k0 + kv * 8;
        asm volatile("cp.async.cg.shared.global [%0], [%1], 16;" :: "r"(dst), "l"(src));
    }
}

__device__ __forceinline__ void ldmA(uint32_t* r, uint32_t base, int m0, int k16, int lane) {
    int m = m0 + (lane & 15);
    int kv = k16 * 2 + (lane >> 4);
    uint32_t addr = base + sw_off(m, kv);
    asm volatile("ldmatrix.sync.aligned.m8n8.x4.shared.b16 {%0,%1,%2,%3}, [%4];"
                 : "=r"(r[0]), "=r"(r[1]), "=r"(r[2]), "=r"(r[3]) : "r"(addr));
}
__device__ __forceinline__ void ldmB(uint32_t* r, uint32_t base, int n0, int k16, int lane) {
    int row = n0 + (lane & 7) + ((lane >> 4) << 3);
    int kv = k16 * 2 + ((lane >> 3) & 1);
    uint32_t addr = base + sw_off(row, kv);
    asm volatile("ldmatrix.sync.aligned.m8n8.x4.shared.b16 {%0,%1,%2,%3}, [%4];"
                 : "=r"(r[0]), "=r"(r[1]), "=r"(r[2]), "=r"(r[3]) : "r"(addr));
}
__device__ __forceinline__ void mmaOp(float* c, const uint32_t* a, const uint32_t* b) {
    asm volatile(
        "mma.sync.aligned.m16n8k16.row.col.f32.bf16.bf16.f32 "
        "{%0,%1,%2,%3},{%4,%5,%6,%7},{%8,%9},{%0,%1,%2,%3};"
        : "+f"(c[0]), "+f"(c[1]), "+f"(c[2]), "+f"(c[3])
        : "r"(a[0]), "r"(a[1]), "r"(a[2]), "r"(a[3]), "r"(b[0]), "r"(b[1]));
}

template <int OUT_SPLIT>
__global__ void __launch_bounds__(256, 1)
gemm_tc(const bf16* __restrict__ aH, const bf16* __restrict__ aL, long aS, int lda,
        const bf16* __restrict__ bH, const bf16* __restrict__ bL, long bS, int ldb,
        float* __restrict__ outF, bf16* __restrict__ oH, bf16* __restrict__ oL,
        long oS, int ldc, const float* __restrict__ rBias,
        const float* __restrict__ cBias, int K,
        const bf16* __restrict__ bH2, const bf16* __restrict__ bL2,
        const float* __restrict__ cBias2,
        bf16* __restrict__ oH2, bf16* __restrict__ oL2)
{
    extern __shared__ char smraw[];
    const uint32_t sb = smem_u32(smraw);

    const int tid = threadIdx.x, wid = tid >> 5, lane = tid & 31;
    const int bn = blockIdx.x * 256, bm = blockIdx.y * 128;
    int bz = blockIdx.z;
    if (bH2 && bz >= BB) {
        bz -= BB;
        bH = bH2; bL = bL2; cBias = cBias2; oH = oH2; oL = oL2;
    }
    const int wm = (wid & 1) * 64;     // 0,64
    const int wn = (wid >> 1) * 64;    // 0,64,128,192

    const bf16* A0 = aH + (long)bz * aS + (long)bm * lda;
    const bf16* A1 = aL + (long)bz * aS + (long)bm * lda;
    const bf16* B0 = bH + (long)bz * bS + (long)bn * ldb;
    const bf16* B1 = bL + (long)bz * bS + (long)bn * ldb;
    const int nch = K >> 5;   // 32-wide chunks

    float acc[4][8][4];
#pragma unroll
    for (int i = 0; i < 4; i++)
#pragma unroll
        for (int j = 0; j < 8; j++)
#pragma unroll
            for (int e = 0; e < 4; e++) acc[i][j][e] = 0.f;

#pragma unroll
    for (int s = 0; s < NSTG - 1; s++) {
        uint32_t st = sb + s * STG_BYTES;
        int k0 = s << 5;
        cpa_A(st,                 A0, lda, k0, tid);
        cpa_A(st + A_TILE_B,      A1, lda, k0, tid);
        cpa_B(st + 2 * A_TILE_B,  B0, ldb, k0, tid);
        cpa_B(st + 2 * A_TILE_B + B_TILE_B, B1, ldb, k0, tid);
        asm volatile("cp.async.commit_group;");
    }

    for (int c = 0; c < nch; c++) {
        asm volatile("cp.async.wait_group 1;");
        __syncthreads();
        if (c + NSTG - 1 < nch) {
            uint32_t st = sb + ((c + NSTG - 1) % NSTG) * STG_BYTES;
            int k0 = (c + NSTG - 1) << 5;
            cpa_A(st,                 A0, lda, k0, tid);
            cpa_A(st + A_TILE_B,      A1, lda, k0, tid);
            cpa_B(st + 2 * A_TILE_B,  B0, ldb, k0, tid);
            cpa_B(st + 2 * A_TILE_B + B_TILE_B, B1, ldb, k0, tid);
        }
        asm volatile("cp.async.commit_group;");

        const uint32_t st = sb + (c % NSTG) * STG_BYTES;
        const uint32_t stB = st + 2 * A_TILE_B;
#pragma unroll
        for (int k16 = 0; k16 < 2; k16++) {
            uint32_t fAh[4][4], fAl[4][4], fB[4][4];
#pragma unroll
            for (int mt = 0; mt < 4; mt++) {
                ldmA(fAh[mt], st,            wm + mt * 16, k16, lane);
                ldmA(fAl[mt], st + A_TILE_B, wm + mt * 16, k16, lane);
            }
            // ---- B hi limb: HH + LH ----
#pragma unroll
            for (int g = 0; g < 4; g++) ldmB(fB[g], stB, wn + g * 16, k16, lane);
#pragma unroll
            for (int mt = 0; mt < 4; mt++)
#pragma unroll
                for (int nt = 0; nt < 8; nt++)
                    mmaOp(acc[mt][nt], fAh[mt], &fB[nt >> 1][(nt & 1) * 2]);
#pragma unroll
            for (int mt = 0; mt < 4; mt++)
#pragma unroll
                for (int nt = 0; nt < 8; nt++)
                    mmaOp(acc[mt][nt], fAl[mt], &fB[nt >> 1][(nt & 1) * 2]);
            // ---- B lo limb: HL (overwrite fB) ----
#pragma unroll
            for (int g = 0; g < 4; g++) ldmB(fB[g], stB + B_TILE_B, wn + g * 16, k16, lane);
#pragma unroll
            for (int mt = 0; mt < 4; mt++)
#pragma unroll
                for (int nt = 0; nt < 8; nt++)
                    mmaOp(acc[mt][nt], fAh[mt], &fB[nt >> 1][(nt & 1) * 2]);
        }
        __syncthreads();
    }

    // epilogue
    const int rr = lane >> 2;
    const int cc2 = (lane & 3) * 2;
#pragma unroll
    for (int mt = 0; mt < 4; mt++) {
#pragma unroll
        for (int nt = 0; nt < 8; nt++) {
            int row0 = bm + wm + mt * 16 + rr;
            int col = bn + wn + nt * 8 + cc2;
            float cb0 = cBias ? cBias[col] : 0.f;
            float cb1 = cBias ? cBias[col + 1] : 0.f;
#pragma unroll
            for (int h = 0; h < 2; h++) {
                int row = row0 + h * 8;
                float rb = rBias ? rBias[row] : 0.f;
                float v0 = acc[mt][nt][h * 2 + 0] + rb + cb0;
                float v1 = acc[mt][nt][h * 2 + 1] + rb + cb1;
                long o = (long)bz * oS + (long)row * ldc + col;
                if (OUT_SPLIT == 0) {
                    *(float2*)(outF + o) = make_float2(v0, v1);
                } else {
                    st_split2(oH + o, oL + o, v0, v1);
                }
            }
        }
    }
}

// ---------------- elementwise kernels ----------------
__global__ void __launch_bounds__(256) split_w4(
    const float* __restrict__ w0, const float* __restrict__ w1,
    const float* __restrict__ w2, const float* __restrict__ w3,
    bf16* __restrict__ h0, bf16* __restrict__ l0,
    bf16* __restrict__ h1, bf16* __restrict__ l1,
    bf16* __restrict__ h2, bf16* __restrict__ l2,
    bf16* __restrict__ h3, bf16* __restrict__ l3)
{
    const int seg = blockIdx.x >> 11;
    const int i = (blockIdx.x & 2047) * 256 + threadIdx.x;
    const float* w = seg == 0 ? w0 : seg == 1 ? w1 : seg == 2 ? w2 : w3;
    bf16* hi = seg == 0 ? h0 : seg == 1 ? h1 : seg == 2 ? h2 : h3;
    bf16* lo = seg == 0 ? l0 : seg == 1 ? l1 : seg == 2 ? l2 : l3;
    float v = w[i];
    bf16 h = __float2bfloat16(v);
    hi[i] = h;
    lo[i] = __float2bfloat16(v - __bfloat162float(h));
}

__global__ void __launch_bounds__(256) xpose_split(const float* __restrict__ x,
                                                   bf16* __restrict__ hi, bf16* __restrict__ lo)
{
    __shared__ float t[32][33];
    const int b = blockIdx.z, n0 = blockIdx.x * 32, c0 = blockIdx.y * 32;
    const int tx = threadIdx.x & 31, ty = threadIdx.x >> 5;
#pragma unroll
    for (int i = 0; i < 4; i++) {
        int r = ty + i * 8;
        t[r][tx] = x[((long)b * CC + c0 + r) * NT + n0 + tx];
    }
    __syncthreads();
#pragma unroll
    for (int i = 0; i < 4; i++) {
        int r = ty + i * 8;
        float v = t[tx][r];
        long o = ((long)b * NT + n0 + r) * CC + c0 + tx;
        bf16 h = __float2bfloat16(v);
        hi[o] = h;
        lo[o] = __float2bfloat16(v - __bfloat162float(h));
    }
}

__global__ void __launch_bounds__(256) softmax_split(const float* __restrict__ f,
                                                     bf16* __restrict__ hi, bf16* __restrict__ lo)
{
    const float4* pv = (const float4*)(f + (size_t)blockIdx.x * NT);
    const int tid = threadIdx.x;
    float4 a = pv[tid], b = pv[tid + 256];
    float m = fmaxf(fmaxf(fmaxf(a.x, a.y), fmaxf(a.z, a.w)),
                    fmaxf(fmaxf(b.x, b.y), fmaxf(b.z, b.w)));
    __shared__ float red[8];
#pragma unroll
    for (int o = 16; o > 0; o >>= 1) m = fmaxf(m, __shfl_xor_sync(~0u, m, o));
    if ((tid & 31) == 0) red[tid >> 5] = m;
    __syncthreads();
    float mm = red[0];
#pragma unroll
    for (int i = 1; i < 8; i++) mm = fmaxf(mm, red[i]);
    __syncthreads();
    a.x = expf(a.x - mm); a.y = expf(a.y - mm); a.z = expf(a.z - mm); a.w = expf(a.w - mm);
    b.x = expf(b.x - mm); b.y = expf(b.y - mm); b.z = expf(b.z - mm); b.w = expf(b.w - mm);
    float s = (a.x + a.y) + (a.z + a.w) + (b.x + b.y) + (b.z + b.w);
#pragma unroll
    for (int o = 16; o > 0; o >>= 1) s += __shfl_xor_sync(~0u, s, o);
    if ((tid & 31) == 0) red[tid >> 5] = s;
    __syncthreads();
    float sum = 0.f;
#pragma unroll
    for (int i = 0; i < 8; i++) sum += red[i];
    float inv = 1.0f / sum;
    size_t off = (size_t)blockIdx.x * NT;
    st_split4(hi + off + tid * 4, lo + off + tid * 4,
              a.x * inv, a.y * inv, a.z * inv, a.w * inv);
    st_split4(hi + off + 1024 + tid * 4, lo + off + 1024 + tid * 4,
              b.x * inv, b.y * inv, b.z * inv, b.w * inv);
}

__global__ void __launch_bounds__(256)
bn_residual(const float* __restrict__ wy, const float* __restrict__ x,
            const float* __restrict__ gamma, const float* __restrict__ beta,
            float* __restrict__ out)
{
    const int c = blockIdx.x, tid = threadIdx.x;
    float vals[32], s = 0.f, ss = 0.f;
#pragma unroll
    for (int b = 0; b < BB; b++) {
        const float* p = wy + ((size_t)b * CC + c) * NT;
#pragma unroll
        for (int j = 0; j < 8; j++) {
            float v = p[tid + j * 256];
            vals[b * 8 + j] = v; s += v; ss += v * v;
        }
    }
    __shared__ float r1[8], r2[8];
#pragma unroll
    for (int o = 16; o > 0; o >>= 1) {
        s += __shfl_xor_sync(~0u, s, o);
        ss += __shfl_xor_sync(~0u, ss, o);
    }
    if ((tid & 31) == 0) { r1[tid >> 5] = s; r2[tid >> 5] = ss; }
    __syncthreads();
    s = 0.f; ss = 0.f;
#pragma unroll
    for (int i = 0; i < 8; i++) { s += r1[i]; ss += r2[i]; }
    const float cnt = (float)(BB * NT);
    float mean = s / cnt;
    float var = ss / cnt - mean * mean;
    float scale = rsqrtf(var + 1e-5f) * gamma[c];
    float shift = beta[c] - mean * scale;
#pragma unroll
    for (int b = 0; b < BB; b++) {
        size_t off = ((size_t)b * CC + c) * NT;
#pragma unroll
        for (int j = 0; j < 8; j++) {
            int n = tid + j * 256;
            out[off + n] = vals[b * 8 + j] * scale + shift + x[off + n];
        }
    }
}

// ---------------------------------------------------------------------------
extern "C" void kernel_launch(void* const* d_in, const int* in_sizes, int n_in,
                              void* d_out, int out_size)
{
    const float* x   = (const float*)d_in[0];
    const float* gw  = (const float*)d_in[1];
    const float* gb  = (const float*)d_in[2];
    const float* tw  = (const float*)d_in[3];
    const float* tb  = (const float*)d_in[4];
    const float* pw  = (const float*)d_in[5];
    const float* pb  = (const float*)d_in[6];
    const float* ww  = (const float*)d_in[7];
    const float* wb  = (const float*)d_in[8];
    const float* bg  = (const float*)d_in[9];
    const float* bbt = (const float*)d_in[10];
    float* out = (float*)d_out;

    bf16 *xTh, *xTl, *wgh, *wgl, *wth, *wtl, *wph, *wpl, *wwh, *wwl;
    bf16 *thh, *thl, *phh, *phl, *gsh, *gsl, *ath, *atl, *yh, *yl;
    float *ff, *wy;
    cudaGetSymbolAddress((void**)&xTh, s_xT_h); cudaGetSymbolAddress((void**)&xTl, s_xT_l);
    cudaGetSymbolAddress((void**)&wgh, s_wg_h); cudaGetSymbolAddress((void**)&wgl, s_wg_l);
    cudaGetSymbolAddress((void**)&wth, s_wt_h); cudaGetSymbolAddress((void**)&wtl, s_wt_l);
    cudaGetSymbolAddress((void**)&wph, s_wp_h); cudaGetSymbolAddress((void**)&wpl, s_wp_l);
    cudaGetSymbolAddress((void**)&wwh, s_ww_h); cudaGetSymbolAddress((void**)&wwl, s_ww_l);
    cudaGetSymbolAddress((void**)&thh, s_th_h); cudaGetSymbolAddress((void**)&thl, s_th_l);
    cudaGetSymbolAddress((void**)&phh, s_ph_h); cudaGetSymbolAddress((void**)&phl, s_ph_l);
    cudaGetSymbolAddress((void**)&gsh, s_gs_h); cudaGetSymbolAddress((void**)&gsl, s_gs_l);
    cudaGetSymbolAddress((void**)&ath, s_at_h); cudaGetSymbolAddress((void**)&atl, s_at_l);
    cudaGetSymbolAddress((void**)&yh,  s_y_h);  cudaGetSymbolAddress((void**)&yl,  s_y_l);
    cudaGetSymbolAddress((void**)&ff,  s_f);    cudaGetSymbolAddress((void**)&wy,  s_wy);

    cudaFuncSetAttribute(gemm_tc<0>, cudaFuncAttributeMaxDynamicSharedMemorySize, SMEM_TOTAL);
    cudaFuncSetAttribute(gemm_tc<1>, cudaFuncAttributeMaxDynamicSharedMemorySize, SMEM_TOTAL);

    split_w4<<<4 * 2048, 256>>>(gw, tw, pw, ww,
                                wgh, wgl, wth, wtl, wph, wpl, wwh, wwl);
    xpose_split<<<dim3(NT / 32, CC / 32, BB), 256>>>(x, xTh, xTl);

    const long sXT = (long)NT * CC, sPR = (long)NT * CIN;
    const long sGS = (long)CIN * NT, sAT = (long)NT * NT, sWY = (long)CC * NT;

    // theta + phi fused (rows=NT, cols=CIN, K=CC; z in [0,8))
    gemm_tc<1><<<dim3(CIN / 256, NT / 128, 2 * BB), 256, SMEM_TOTAL>>>(
        xTh, xTl, sXT, CC, wth, wtl, 0, CC, nullptr, thh, thl, sPR, CIN, nullptr, tb, CC,
        wph, wpl, pb, phh, phl);
    // g_s[b,o,m] (rows=CIN, cols=NT, K=CC)
    gemm_tc<1><<<dim3(NT / 256, CIN / 128, BB), 256, SMEM_TOTAL>>>(
        wgh, wgl, 0, CC, xTh, xTl, sXT, CC, nullptr, gsh, gsl, sGS, NT, gb, nullptr, CC,
        nullptr, nullptr, nullptr, nullptr, nullptr);
    // f[b,n,m] (rows=NT, cols=NT, K=CIN)
    gemm_tc<0><<<dim3(NT / 256, NT / 128, BB), 256, SMEM_TOTAL>>>(
        thh, thl, sPR, CIN, phh, phl, sPR, CIN, ff, nullptr, nullptr, sAT, NT, nullptr, nullptr, CIN,
        nullptr, nullptr, nullptr, nullptr, nullptr);
    // softmax -> split attn
    softmax_split<<<BB * NT, 256>>>(ff, ath, atl);
    // y[b,n,o] (rows=NT, cols=CIN, K=NT)
    gemm_tc<1><<<dim3(CIN / 256, NT / 128, BB), 256, SMEM_TOTAL>>>(
        ath, atl, sAT, NT, gsh, gsl, sGS, NT, nullptr, yh, yl, sPR, CIN, nullptr, nullptr, NT,
        nullptr, nullptr, nullptr, nullptr, nullptr);
    // w_y[b,c,n] (rows=CC, cols=NT, K=CIN)
    gemm_tc<0><<<dim3(NT / 256, CC / 128, BB), 256, SMEM_TOTAL>>>(
        wwh, wwl, 0, CIN, yh, yl, sPR, CIN, wy, nullptr, nullptr, sWY, NT, wb, nullptr, CIN,
        nullptr, nullptr, nullptr, nullptr, nullptr);
    // BN + residual
    bn_residual<<<CC, 256>>>(wy, x, bg, bbt, out);
}

// round 9
// speedup vs baseline: 1.0394x; 1.0394x over previous
#include <cuda_runtime.h>
#include <cuda_bf16.h>
#include <cstdint>

typedef __nv_bfloat16 bf16;

#define BB 4
#define CC 1024
#define CIN 512
#define NT 2048

// ---------------- static scratch ----------------
__device__ __align__(256) bf16 s_xT_h[BB * NT * CC];
__device__ __align__(256) bf16 s_xT_l[BB * NT * CC];
__device__ __align__(256) bf16 s_wg_h[CIN * CC], s_wg_l[CIN * CC];
__device__ __align__(256) bf16 s_wt_h[CIN * CC], s_wt_l[CIN * CC];
__device__ __align__(256) bf16 s_wp_h[CIN * CC], s_wp_l[CIN * CC];
__device__ __align__(256) bf16 s_ww_h[CC * CIN], s_ww_l[CC * CIN];
__device__ __align__(256) bf16 s_th_h[BB * NT * CIN], s_th_l[BB * NT * CIN];
__device__ __align__(256) bf16 s_ph_h[BB * NT * CIN], s_ph_l[BB * NT * CIN];
__device__ __align__(256) bf16 s_gs_h[BB * CIN * NT], s_gs_l[BB * CIN * NT];
__device__ __align__(256) float s_f[BB * NT * NT];
__device__ __align__(256) bf16 s_at_h[BB * NT * NT], s_at_l[BB * NT * NT];
__device__ __align__(256) bf16 s_y_h[BB * NT * CIN], s_y_l[BB * NT * CIN];
__device__ __align__(256) float s_wy[BB * CC * NT];

// ---------------- helpers ----------------
__device__ __forceinline__ uint32_t smem_u32(const void* p) {
    uint32_t a;
    asm("{ .reg .u64 t; cvta.to.shared.u64 t, %1; cvt.u32.u64 %0, t; }" : "=r"(a) : "l"(p));
    return a;
}
__device__ __forceinline__ void st_split2(bf16* hi, bf16* lo, float v0, float v1) {
    bf16 h0 = __float2bfloat16(v0), h1 = __float2bfloat16(v1);
    *(uint32_t*)hi = (uint32_t)__bfloat16_as_ushort(h0) |
                     ((uint32_t)__bfloat16_as_ushort(h1) << 16);
    bf16 l0 = __float2bfloat16(v0 - __bfloat162float(h0));
    bf16 l1 = __float2bfloat16(v1 - __bfloat162float(h1));
    *(uint32_t*)lo = (uint32_t)__bfloat16_as_ushort(l0) |
                     ((uint32_t)__bfloat16_as_ushort(l1) << 16);
}
__device__ __forceinline__ void st_split4(bf16* hi, bf16* lo, float v0, float v1, float v2, float v3) {
    st_split2(hi, lo, v0, v1);
    st_split2(hi + 2, lo + 2, v2, v3);
}

// ---------------- HMMA GEMM ----------------
// D[r,c] = sum_k (Ah+Al)[r,k] * (Bh+Bl)[c,k]  via HH + HL + LH
// CTA tile 128x128, K-chunk 32, 8 warps, warp tile 64x32, 3-stage cp.async.
// 96 KB smem/CTA -> 2 CTAs per SM so one CTA's MMAs cover the other's barriers.
#define NSTG 3
#define TILE_B 8192              // 128 x 32 bf16
#define STG_BYTES (4 * TILE_B)   // Ah/Al/Bh/Bl = 32 KB
#define SMEM_TOTAL (NSTG * STG_BYTES)   // 96 KB

// swizzled byte offset of 16B vector (row, kv) in a 128x32 bf16 tile (64B rows)
__device__ __forceinline__ uint32_t sw_off(int row, int kv) {
    return (uint32_t)(row * 64 + ((kv ^ ((row >> 1) & 3)) << 4));
}

__device__ __forceinline__ void cpa_tile(uint32_t sdst, const bf16* __restrict__ g,
                                         int ld, int k0, int tid) {
#pragma unroll
    for (int i = 0; i < 2; i++) {
        int idx = tid + i * 256;       // 0..511
        int row = idx >> 2;            // 0..127
        int kv  = idx & 3;
        uint32_t dst = sdst + sw_off(row, kv);
        const void* src = g + (long)row * ld + k0 + kv * 8;
        asm volatile("cp.async.cg.shared.global [%0], [%1], 16;" :: "r"(dst), "l"(src));
    }
}

__device__ __forceinline__ void ldmA(uint32_t* r, uint32_t base, int m0, int k16, int lane) {
    int m = m0 + (lane & 15);
    int kv = k16 * 2 + (lane >> 4);
    uint32_t addr = base + sw_off(m, kv);
    asm volatile("ldmatrix.sync.aligned.m8n8.x4.shared.b16 {%0,%1,%2,%3}, [%4];"
                 : "=r"(r[0]), "=r"(r[1]), "=r"(r[2]), "=r"(r[3]) : "r"(addr));
}
__device__ __forceinline__ void ldmB(uint32_t* r, uint32_t base, int n0, int k16, int lane) {
    int row = n0 + (lane & 7) + ((lane >> 4) << 3);
    int kv = k16 * 2 + ((lane >> 3) & 1);
    uint32_t addr = base + sw_off(row, kv);
    asm volatile("ldmatrix.sync.aligned.m8n8.x4.shared.b16 {%0,%1,%2,%3}, [%4];"
                 : "=r"(r[0]), "=r"(r[1]), "=r"(r[2]), "=r"(r[3]) : "r"(addr));
}
__device__ __forceinline__ void mmaOp(float* c, const uint32_t* a, const uint32_t* b) {
    asm volatile(
        "mma.sync.aligned.m16n8k16.row.col.f32.bf16.bf16.f32 "
        "{%0,%1,%2,%3},{%4,%5,%6,%7},{%8,%9},{%0,%1,%2,%3};"
        : "+f"(c[0]), "+f"(c[1]), "+f"(c[2]), "+f"(c[3])
        : "r"(a[0]), "r"(a[1]), "r"(a[2]), "r"(a[3]), "r"(b[0]), "r"(b[1]));
}

template <int OUT_SPLIT>
__global__ void __launch_bounds__(256, 2)
gemm_tc(const bf16* __restrict__ aH, const bf16* __restrict__ aL, long aS, int lda,
        const bf16* __restrict__ bH, const bf16* __restrict__ bL, long bS, int ldb,
        float* __restrict__ outF, bf16* __restrict__ oH, bf16* __restrict__ oL,
        long oS, int ldc, const float* __restrict__ rBias,
        const float* __restrict__ cBias, int K,
        const bf16* __restrict__ bH2, const bf16* __restrict__ bL2,
        const float* __restrict__ cBias2,
        bf16* __restrict__ oH2, bf16* __restrict__ oL2)
{
    extern __shared__ char smraw[];
    const uint32_t sb = smem_u32(smraw);

    const int tid = threadIdx.x, wid = tid >> 5, lane = tid & 31;
    const int bn = blockIdx.x * 128, bm = blockIdx.y * 128;
    int bz = blockIdx.z;
    if (bH2 && bz >= BB) {
        bz -= BB;
        bH = bH2; bL = bL2; cBias = cBias2; oH = oH2; oL = oL2;
    }
    const int wm = (wid >> 2) * 64;   // 0,64
    const int wn = (wid & 3) * 32;    // 0..96

    const bf16* A0 = aH + (long)bz * aS + (long)bm * lda;
    const bf16* A1 = aL + (long)bz * aS + (long)bm * lda;
    const bf16* B0 = bH + (long)bz * bS + (long)bn * ldb;
    const bf16* B1 = bL + (long)bz * bS + (long)bn * ldb;
    const int nch = K >> 5;   // 32-wide chunks

    float acc[4][4][4];
#pragma unroll
    for (int i = 0; i < 4; i++)
#pragma unroll
        for (int j = 0; j < 4; j++)
#pragma unroll
            for (int e = 0; e < 4; e++) acc[i][j][e] = 0.f;

#pragma unroll
    for (int s = 0; s < NSTG - 1; s++) {
        uint32_t st = sb + s * STG_BYTES;
        int k0 = s << 5;
        cpa_tile(st,              A0, lda, k0, tid);
        cpa_tile(st + TILE_B,     A1, lda, k0, tid);
        cpa_tile(st + 2 * TILE_B, B0, ldb, k0, tid);
        cpa_tile(st + 3 * TILE_B, B1, ldb, k0, tid);
        asm volatile("cp.async.commit_group;");
    }

    for (int c = 0; c < nch; c++) {
        asm volatile("cp.async.wait_group 1;");
        __syncthreads();
        if (c + NSTG - 1 < nch) {
            uint32_t st = sb + ((c + NSTG - 1) % NSTG) * STG_BYTES;
            int k0 = (c + NSTG - 1) << 5;
            cpa_tile(st,              A0, lda, k0, tid);
            cpa_tile(st + TILE_B,     A1, lda, k0, tid);
            cpa_tile(st + 2 * TILE_B, B0, ldb, k0, tid);
            cpa_tile(st + 3 * TILE_B, B1, ldb, k0, tid);
        }
        asm volatile("cp.async.commit_group;");

        const uint32_t st = sb + (c % NSTG) * STG_BYTES;
#pragma unroll
        for (int k16 = 0; k16 < 2; k16++) {
            uint32_t fAh[4][4], fAl[4][4], fBh[2][4], fBl[2][4];
#pragma unroll
            for (int mt = 0; mt < 4; mt++) {
                ldmA(fAh[mt], st,          wm + mt * 16, k16, lane);
                ldmA(fAl[mt], st + TILE_B, wm + mt * 16, k16, lane);
            }
            ldmB(fBh[0], st + 2 * TILE_B, wn,      k16, lane);
            ldmB(fBh[1], st + 2 * TILE_B, wn + 16, k16, lane);
            ldmB(fBl[0], st + 3 * TILE_B, wn,      k16, lane);
            ldmB(fBl[1], st + 3 * TILE_B, wn + 16, k16, lane);
#pragma unroll
            for (int mt = 0; mt < 4; mt++)
#pragma unroll
                for (int nt = 0; nt < 4; nt++)
                    mmaOp(acc[mt][nt], fAh[mt], &fBh[nt >> 1][(nt & 1) * 2]);
#pragma unroll
            for (int mt = 0; mt < 4; mt++)
#pragma unroll
                for (int nt = 0; nt < 4; nt++)
                    mmaOp(acc[mt][nt], fAh[mt], &fBl[nt >> 1][(nt & 1) * 2]);
#pragma unroll
            for (int mt = 0; mt < 4; mt++)
#pragma unroll
                for (int nt = 0; nt < 4; nt++)
                    mmaOp(acc[mt][nt], fAl[mt], &fBh[nt >> 1][(nt & 1) * 2]);
        }
        __syncthreads();
    }

    // epilogue
    const int rr = lane >> 2;
    const int cc2 = (lane & 3) * 2;
#pragma unroll
    for (int mt = 0; mt < 4; mt++) {
#pragma unroll
        for (int nt = 0; nt < 4; nt++) {
            int row0 = bm + wm + mt * 16 + rr;
            int col = bn + wn + nt * 8 + cc2;
            float cb0 = cBias ? cBias[col] : 0.f;
            float cb1 = cBias ? cBias[col + 1] : 0.f;
#pragma unroll
            for (int h = 0; h < 2; h++) {
                int row = row0 + h * 8;
                float rb = rBias ? rBias[row] : 0.f;
                float v0 = acc[mt][nt][h * 2 + 0] + rb + cb0;
                float v1 = acc[mt][nt][h * 2 + 1] + rb + cb1;
                long o = (long)bz * oS + (long)row * ldc + col;
                if (OUT_SPLIT == 0) {
                    *(float2*)(outF + o) = make_float2(v0, v1);
                } else {
                    st_split2(oH + o, oL + o, v0, v1);
                }
            }
        }
    }
}

// ---------------- elementwise kernels ----------------
__global__ void __launch_bounds__(256) split_w4(
    const float* __restrict__ w0, const float* __restrict__ w1,
    const float* __restrict__ w2, const float* __restrict__ w3,
    bf16* __restrict__ h0, bf16* __restrict__ l0,
    bf16* __restrict__ h1, bf16* __restrict__ l1,
    bf16* __restrict__ h2, bf16* __restrict__ l2,
    bf16* __restrict__ h3, bf16* __restrict__ l3)
{
    const int seg = blockIdx.x >> 11;
    const int i = (blockIdx.x & 2047) * 256 + threadIdx.x;
    const float* w = seg == 0 ? w0 : seg == 1 ? w1 : seg == 2 ? w2 : w3;
    bf16* hi = seg == 0 ? h0 : seg == 1 ? h1 : seg == 2 ? h2 : h3;
    bf16* lo = seg == 0 ? l0 : seg == 1 ? l1 : seg == 2 ? l2 : l3;
    float v = w[i];
    bf16 h = __float2bfloat16(v);
    hi[i] = h;
    lo[i] = __float2bfloat16(v - __bfloat162float(h));
}

__global__ void __launch_bounds__(256) xpose_split(const float* __restrict__ x,
                                                   bf16* __restrict__ hi, bf16* __restrict__ lo)
{
    __shared__ float t[32][33];
    const int b = blockIdx.z, n0 = blockIdx.x * 32, c0 = blockIdx.y * 32;
    const int tx = threadIdx.x & 31, ty = threadIdx.x >> 5;
#pragma unroll
    for (int i = 0; i < 4; i++) {
        int r = ty + i * 8;
        t[r][tx] = x[((long)b * CC + c0 + r) * NT + n0 + tx];
    }
    __syncthreads();
#pragma unroll
    for (int i = 0; i < 4; i++) {
        int r = ty + i * 8;
        float v = t[tx][r];
        long o = ((long)b * NT + n0 + r) * CC + c0 + tx;
        bf16 h = __float2bfloat16(v);
        hi[o] = h;
        lo[o] = __float2bfloat16(v - __bfloat162float(h));
    }
}

__global__ void __launch_bounds__(256) softmax_split(const float* __restrict__ f,
                                                     bf16* __restrict__ hi, bf16* __restrict__ lo)
{
    const float4* pv = (const float4*)(f + (size_t)blockIdx.x * NT);
    const int tid = threadIdx.x;
    float4 a = pv[tid], b = pv[tid + 256];
    float m = fmaxf(fmaxf(fmaxf(a.x, a.y), fmaxf(a.z, a.w)),
                    fmaxf(fmaxf(b.x, b.y), fmaxf(b.z, b.w)));
    __shared__ float red[8];
#pragma unroll
    for (int o = 16; o > 0; o >>= 1) m = fmaxf(m, __shfl_xor_sync(~0u, m, o));
    if ((tid & 31) == 0) red[tid >> 5] = m;
    __syncthreads();
    float mm = red[0];
#pragma unroll
    for (int i = 1; i < 8; i++) mm = fmaxf(mm, red[i]);
    __syncthreads();
    a.x = expf(a.x - mm); a.y = expf(a.y - mm); a.z = expf(a.z - mm); a.w = expf(a.w - mm);
    b.x = expf(b.x - mm); b.y = expf(b.y - mm); b.z = expf(b.z - mm); b.w = expf(b.w - mm);
    float s = (a.x + a.y) + (a.z + a.w) + (b.x + b.y) + (b.z + b.w);
#pragma unroll
    for (int o = 16; o > 0; o >>= 1) s += __shfl_xor_sync(~0u, s, o);
    if ((tid & 31) == 0) red[tid >> 5] = s;
    __syncthreads();
    float sum = 0.f;
#pragma unroll
    for (int i = 0; i < 8; i++) sum += red[i];
    float inv = 1.0f / sum;
    size_t off = (size_t)blockIdx.x * NT;
    st_split4(hi + off + tid * 4, lo + off + tid * 4,
              a.x * inv, a.y * inv, a.z * inv, a.w * inv);
    st_split4(hi + off + 1024 + tid * 4, lo + off + 1024 + tid * 4,
              b.x * inv, b.y * inv, b.z * inv, b.w * inv);
}

__global__ void __launch_bounds__(256)
bn_residual(const float* __restrict__ wy, const float* __restrict__ x,
            const float* __restrict__ gamma, const float* __restrict__ beta,
            float* __restrict__ out)
{
    const int c = blockIdx.x, tid = threadIdx.x;
    float vals[32], s = 0.f, ss = 0.f;
#pragma unroll
    for (int b = 0; b < BB; b++) {
        const float* p = wy + ((size_t)b * CC + c) * NT;
#pragma unroll
        for (int j = 0; j < 8; j++) {
            float v = p[tid + j * 256];
            vals[b * 8 + j] = v; s += v; ss += v * v;
        }
    }
    __shared__ float r1[8], r2[8];
#pragma unroll
    for (int o = 16; o > 0; o >>= 1) {
        s += __shfl_xor_sync(~0u, s, o);
        ss += __shfl_xor_sync(~0u, ss, o);
    }
    if ((tid & 31) == 0) { r1[tid >> 5] = s; r2[tid >> 5] = ss; }
    __syncthreads();
    s = 0.f; ss = 0.f;
#pragma unroll
    for (int i = 0; i < 8; i++) { s += r1[i]; ss += r2[i]; }
    const float cnt = (float)(BB * NT);
    float mean = s / cnt;
    float var = ss / cnt - mean * mean;
    float scale = rsqrtf(var + 1e-5f) * gamma[c];
    float shift = beta[c] - mean * scale;
#pragma unroll
    for (int b = 0; b < BB; b++) {
        size_t off = ((size_t)b * CC + c) * NT;
#pragma unroll
        for (int j = 0; j < 8; j++) {
            int n = tid + j * 256;
            out[off + n] = vals[b * 8 + j] * scale + shift + x[off + n];
        }
    }
}

// ---------------------------------------------------------------------------
extern "C" void kernel_launch(void* const* d_in, const int* in_sizes, int n_in,
                              void* d_out, int out_size)
{
    const float* x   = (const float*)d_in[0];
    const float* gw  = (const float*)d_in[1];
    const float* gb  = (const float*)d_in[2];
    const float* tw  = (const float*)d_in[3];
    const float* tb  = (const float*)d_in[4];
    const float* pw  = (const float*)d_in[5];
    const float* pb  = (const float*)d_in[6];
    const float* ww  = (const float*)d_in[7];
    const float* wb  = (const float*)d_in[8];
    const float* bg  = (const float*)d_in[9];
    const float* bbt = (const float*)d_in[10];
    float* out = (float*)d_out;

    bf16 *xTh, *xTl, *wgh, *wgl, *wth, *wtl, *wph, *wpl, *wwh, *wwl;
    bf16 *thh, *thl, *phh, *phl, *gsh, *gsl, *ath, *atl, *yh, *yl;
    float *ff, *wy;
    cudaGetSymbolAddress((void**)&xTh, s_xT_h); cudaGetSymbolAddress((void**)&xTl, s_xT_l);
    cudaGetSymbolAddress((void**)&wgh, s_wg_h); cudaGetSymbolAddress((void**)&wgl, s_wg_l);
    cudaGetSymbolAddress((void**)&wth, s_wt_h); cudaGetSymbolAddress((void**)&wtl, s_wt_l);
    cudaGetSymbolAddress((void**)&wph, s_wp_h); cudaGetSymbolAddress((void**)&wpl, s_wp_l);
    cudaGetSymbolAddress((void**)&wwh, s_ww_h); cudaGetSymbolAddress((void**)&wwl, s_ww_l);
    cudaGetSymbolAddress((void**)&thh, s_th_h); cudaGetSymbolAddress((void**)&thl, s_th_l);
    cudaGetSymbolAddress((void**)&phh, s_ph_h); cudaGetSymbolAddress((void**)&phl, s_ph_l);
    cudaGetSymbolAddress((void**)&gsh, s_gs_h); cudaGetSymbolAddress((void**)&gsl, s_gs_l);
    cudaGetSymbolAddress((void**)&ath, s_at_h); cudaGetSymbolAddress((void**)&atl, s_at_l);
    cudaGetSymbolAddress((void**)&yh,  s_y_h);  cudaGetSymbolAddress((void**)&yl,  s_y_l);
    cudaGetSymbolAddress((void**)&ff,  s_f);    cudaGetSymbolAddress((void**)&wy,  s_wy);

    cudaFuncSetAttribute(gemm_tc<0>, cudaFuncAttributeMaxDynamicSharedMemorySize, SMEM_TOTAL);
    cudaFuncSetAttribute(gemm_tc<1>, cudaFuncAttributeMaxDynamicSharedMemorySize, SMEM_TOTAL);

    split_w4<<<4 * 2048, 256>>>(gw, tw, pw, ww,
                                wgh, wgl, wth, wtl, wph, wpl, wwh, wwl);
    xpose_split<<<dim3(NT / 32, CC / 32, BB), 256>>>(x, xTh, xTl);

    const long sXT = (long)NT * CC, sPR = (long)NT * CIN;
    const long sGS = (long)CIN * NT, sAT = (long)NT * NT, sWY = (long)CC * NT;

    // theta + phi fused (rows=NT, cols=CIN, K=CC; z in [0,8))
    gemm_tc<1><<<dim3(CIN / 128, NT / 128, 2 * BB), 256, SMEM_TOTAL>>>(
        xTh, xTl, sXT, CC, wth, wtl, 0, CC, nullptr, thh, thl, sPR, CIN, nullptr, tb, CC,
        wph, wpl, pb, phh, phl);
    // g_s[b,o,m] (rows=CIN, cols=NT, K=CC)
    gemm_tc<1><<<dim3(NT / 128, CIN / 128, BB), 256, SMEM_TOTAL>>>(
        wgh, wgl, 0, CC, xTh, xTl, sXT, CC, nullptr, gsh, gsl, sGS, NT, gb, nullptr, CC,
        nullptr, nullptr, nullptr, nullptr, nullptr);
    // f[b,n,m] (rows=NT, cols=NT, K=CIN)
    gemm_tc<0><<<dim3(NT / 128, NT / 128, BB), 256, SMEM_TOTAL>>>(
        thh, thl, sPR, CIN, phh, phl, sPR, CIN, ff, nullptr, nullptr, sAT, NT, nullptr, nullptr, CIN,
        nullptr, nullptr, nullptr, nullptr, nullptr);
    // softmax -> split attn
    softmax_split<<<BB * NT, 256>>>(ff, ath, atl);
    // y[b,n,o] (rows=NT, cols=CIN, K=NT)
    gemm_tc<1><<<dim3(CIN / 128, NT / 128, BB), 256, SMEM_TOTAL>>>(
        ath, atl, sAT, NT, gsh, gsl, sGS, NT, nullptr, yh, yl, sPR, CIN, nullptr, nullptr, NT,
        nullptr, nullptr, nullptr, nullptr, nullptr);
    // w_y[b,c,n] (rows=CC, cols=NT, K=CIN)
    gemm_tc<0><<<dim3(NT / 128, CC / 128, BB), 256, SMEM_TOTAL>>>(
        wwh, wwl, 0, CIN, yh, yl, sPR, CIN, wy, nullptr, nullptr, sWY, NT, wb, nullptr, CIN,
        nullptr, nullptr, nullptr, nullptr, nullptr);
    // BN + residual
    bn_residual<<<CC, 256>>>(wy, x, bg, bbt, out);
}

// round 10
// speedup vs baseline: 1.2090x; 1.1632x over previous
#include <cuda_runtime.h>
#include <cuda_bf16.h>
#include <cuda_fp16.h>
#include <cstdint>

typedef __nv_bfloat16 bf16;

#define BB 4
#define CC 1024
#define CIN 512
#define NT 2048

// ---------------- static scratch ----------------
// logit path (bf16 2-limb)
__device__ __align__(256) bf16 s_xT_h[BB * NT * CC];
__device__ __align__(256) bf16 s_xT_l[BB * NT * CC];
__device__ __align__(256) bf16 s_wt_h[CIN * CC], s_wt_l[CIN * CC];
__device__ __align__(256) bf16 s_wp_h[CIN * CC], s_wp_l[CIN * CC];
__device__ __align__(256) bf16 s_th_h[BB * NT * CIN], s_th_l[BB * NT * CIN];
__device__ __align__(256) bf16 s_ph_h[BB * NT * CIN], s_ph_l[BB * NT * CIN];
__device__ __align__(256) float s_f[BB * NT * NT];
// value path (fp16)
__device__ __align__(256) __half s_xT_f[BB * NT * CC];          // single-limb x
__device__ __align__(256) __half s_wgH[CIN * CC], s_wgL[CIN * CC];
__device__ __align__(256) __half s_wwH[CC * CIN], s_wwL[CC * CIN];
__device__ __align__(256) __half s_gs[BB * CIN * NT];           // g (b,o,m) single fp16
__device__ __align__(256) __half s_atH[BB * NT * NT], s_atL[BB * NT * NT];
__device__ __align__(256) __half s_y[BB * NT * CIN];            // y (b,n,o) single fp16
__device__ __align__(256) float s_wy[BB * CC * NT];

// ---------------- helpers ----------------
__device__ __forceinline__ uint32_t smem_u32(const void* p) {
    uint32_t a;
    asm("{ .reg .u64 t; cvta.to.shared.u64 t, %1; cvt.u32.u64 %0, t; }" : "=r"(a) : "l"(p));
    return a;
}
__device__ __forceinline__ void st_split2(bf16* hi, bf16* lo, float v0, float v1) {
    bf16 h0 = __float2bfloat16(v0), h1 = __float2bfloat16(v1);
    *(uint32_t*)hi = (uint32_t)__bfloat16_as_ushort(h0) |
                     ((uint32_t)__bfloat16_as_ushort(h1) << 16);
    bf16 l0 = __float2bfloat16(v0 - __bfloat162float(h0));
    bf16 l1 = __float2bfloat16(v1 - __bfloat162float(h1));
    *(uint32_t*)lo = (uint32_t)__bfloat16_as_ushort(l0) |
                     ((uint32_t)__bfloat16_as_ushort(l1) << 16);
}
__device__ __forceinline__ void st_splitH2(__half* hi, __half* lo, float v0, float v1) {
    __half h0 = __float2half_rn(v0), h1 = __float2half_rn(v1);
    *(half2*)hi = __halves2half2(h0, h1);
    __half l0 = __float2half_rn(v0 - __half2float(h0));
    __half l1 = __float2half_rn(v1 - __half2float(h1));
    *(half2*)lo = __halves2half2(l0, l1);
}

// ---------------- HMMA GEMM ----------------
// F16==0: bf16, B 2-limb, 3 products (HH+HL+LH)
// F16==1: fp16, B 1-limb, 2 products ((Ah+Al)*B)
// CTA tile 128x128, K-chunk 32, 8 warps, warp tile 64x32, 3-stage cp.async, 2 CTA/SM.
#define NSTG 3
#define TILE_B 8192
#define SMEM_BF  (NSTG * 4 * TILE_B)   // 96 KB
#define SMEM_F16 (NSTG * 3 * TILE_B)   // 72 KB

__device__ __forceinline__ uint32_t sw_off(int row, int kv) {
    return (uint32_t)(row * 64 + ((kv ^ ((row >> 1) & 3)) << 4));
}
__device__ __forceinline__ void cpa_tile(uint32_t sdst, const bf16* __restrict__ g,
                                         int ld, int k0, int tid) {
#pragma unroll
    for (int i = 0; i < 2; i++) {
        int idx = tid + i * 256;
        int row = idx >> 2;
        int kv  = idx & 3;
        uint32_t dst = sdst + sw_off(row, kv);
        const void* src = g + (long)row * ld + k0 + kv * 8;
        asm volatile("cp.async.cg.shared.global [%0], [%1], 16;" :: "r"(dst), "l"(src));
    }
}
__device__ __forceinline__ void ldmA(uint32_t* r, uint32_t base, int m0, int k16, int lane) {
    int m = m0 + (lane & 15);
    int kv = k16 * 2 + (lane >> 4);
    uint32_t addr = base + sw_off(m, kv);
    asm volatile("ldmatrix.sync.aligned.m8n8.x4.shared.b16 {%0,%1,%2,%3}, [%4];"
                 : "=r"(r[0]), "=r"(r[1]), "=r"(r[2]), "=r"(r[3]) : "r"(addr));
}
__device__ __forceinline__ void ldmB(uint32_t* r, uint32_t base, int n0, int k16, int lane) {
    int row = n0 + (lane & 7) + ((lane >> 4) << 3);
    int kv = k16 * 2 + ((lane >> 3) & 1);
    uint32_t addr = base + sw_off(row, kv);
    asm volatile("ldmatrix.sync.aligned.m8n8.x4.shared.b16 {%0,%1,%2,%3}, [%4];"
                 : "=r"(r[0]), "=r"(r[1]), "=r"(r[2]), "=r"(r[3]) : "r"(addr));
}
__device__ __forceinline__ void mmaB(float* c, const uint32_t* a, const uint32_t* b) {
    asm volatile(
        "mma.sync.aligned.m16n8k16.row.col.f32.bf16.bf16.f32 "
        "{%0,%1,%2,%3},{%4,%5,%6,%7},{%8,%9},{%0,%1,%2,%3};"
        : "+f"(c[0]), "+f"(c[1]), "+f"(c[2]), "+f"(c[3])
        : "r"(a[0]), "r"(a[1]), "r"(a[2]), "r"(a[3]), "r"(b[0]), "r"(b[1]));
}
__device__ __forceinline__ void mmaH(float* c, const uint32_t* a, const uint32_t* b) {
    asm volatile(
        "mma.sync.aligned.m16n8k16.row.col.f32.f16.f16.f32 "
        "{%0,%1,%2,%3},{%4,%5,%6,%7},{%8,%9},{%0,%1,%2,%3};"
        : "+f"(c[0]), "+f"(c[1]), "+f"(c[2]), "+f"(c[3])
        : "r"(a[0]), "r"(a[1]), "r"(a[2]), "r"(a[3]), "r"(b[0]), "r"(b[1]));
}

// OUT: 0 = fp32 (+rBias,+cBias), 1 = split bf16 (+biases), 2 = single fp16 (+rBias)
template <int OUT, int F16>
__global__ void __launch_bounds__(256, 2)
gemm_tc(const bf16* __restrict__ aH, const bf16* __restrict__ aL, long aS, int lda,
        const bf16* __restrict__ bH, const bf16* __restrict__ bL, long bS, int ldb,
        float* __restrict__ outF, bf16* __restrict__ oH, bf16* __restrict__ oL,
        long oS, int ldc, const float* __restrict__ rBias,
        const float* __restrict__ cBias, int K,
        const bf16* __restrict__ bH2, const bf16* __restrict__ bL2,
        const float* __restrict__ cBias2,
        bf16* __restrict__ oH2, bf16* __restrict__ oL2)
{
    constexpr int STGB = (F16 ? 3 : 4) * TILE_B;
    extern __shared__ char smraw[];
    const uint32_t sb = smem_u32(smraw);

    const int tid = threadIdx.x, wid = tid >> 5, lane = tid & 31;
    const int bn = blockIdx.x * 128, bm = blockIdx.y * 128;
    int bz = blockIdx.z;
    if (bH2 && bz >= BB) {
        bz -= BB;
        bH = bH2; bL = bL2; cBias = cBias2; oH = oH2; oL = oL2;
    }
    const int wm = (wid >> 2) * 64;
    const int wn = (wid & 3) * 32;

    const bf16* A0 = aH + (long)bz * aS + (long)bm * lda;
    const bf16* A1 = aL + (long)bz * aS + (long)bm * lda;
    const bf16* B0 = bH + (long)bz * bS + (long)bn * ldb;
    const bf16* B1 = F16 ? nullptr : bL + (long)bz * bS + (long)bn * ldb;
    const int nch = K >> 5;

    float acc[4][4][4];
#pragma unroll
    for (int i = 0; i < 4; i++)
#pragma unroll
        for (int j = 0; j < 4; j++)
#pragma unroll
            for (int e = 0; e < 4; e++) acc[i][j][e] = 0.f;

#pragma unroll
    for (int s = 0; s < NSTG - 1; s++) {
        uint32_t st = sb + s * STGB;
        int k0 = s << 5;
        cpa_tile(st,              A0, lda, k0, tid);
        cpa_tile(st + TILE_B,     A1, lda, k0, tid);
        cpa_tile(st + 2 * TILE_B, B0, ldb, k0, tid);
        if (!F16) cpa_tile(st + 3 * TILE_B, B1, ldb, k0, tid);
        asm volatile("cp.async.commit_group;");
    }

    for (int c = 0; c < nch; c++) {
        asm volatile("cp.async.wait_group 1;");
        __syncthreads();
        if (c + NSTG - 1 < nch) {
            uint32_t st = sb + ((c + NSTG - 1) % NSTG) * STGB;
            int k0 = (c + NSTG - 1) << 5;
            cpa_tile(st,              A0, lda, k0, tid);
            cpa_tile(st + TILE_B,     A1, lda, k0, tid);
            cpa_tile(st + 2 * TILE_B, B0, ldb, k0, tid);
            if (!F16) cpa_tile(st + 3 * TILE_B, B1, ldb, k0, tid);
        }
        asm volatile("cp.async.commit_group;");

        const uint32_t st = sb + (c % NSTG) * STGB;
#pragma unroll
        for (int k16 = 0; k16 < 2; k16++) {
            uint32_t fAh[4][4], fAl[4][4];
#pragma unroll
            for (int mt = 0; mt < 4; mt++) {
                ldmA(fAh[mt], st,          wm + mt * 16, k16, lane);
                ldmA(fAl[mt], st + TILE_B, wm + mt * 16, k16, lane);
            }
            if (F16) {
                uint32_t fB[2][4];
                ldmB(fB[0], st + 2 * TILE_B, wn,      k16, lane);
                ldmB(fB[1], st + 2 * TILE_B, wn + 16, k16, lane);
#pragma unroll
                for (int mt = 0; mt < 4; mt++)
#pragma unroll
                    for (int nt = 0; nt < 4; nt++)
                        mmaH(acc[mt][nt], fAh[mt], &fB[nt >> 1][(nt & 1) * 2]);
#pragma unroll
                for (int mt = 0; mt < 4; mt++)
#pragma unroll
                    for (int nt = 0; nt < 4; nt++)
                        mmaH(acc[mt][nt], fAl[mt], &fB[nt >> 1][(nt & 1) * 2]);
            } else {
                uint32_t fBh[2][4], fBl[2][4];
                ldmB(fBh[0], st + 2 * TILE_B, wn,      k16, lane);
                ldmB(fBh[1], st + 2 * TILE_B, wn + 16, k16, lane);
                ldmB(fBl[0], st + 3 * TILE_B, wn,      k16, lane);
                ldmB(fBl[1], st + 3 * TILE_B, wn + 16, k16, lane);
#pragma unroll
                for (int mt = 0; mt < 4; mt++)
#pragma unroll
                    for (int nt = 0; nt < 4; nt++)
                        mmaB(acc[mt][nt], fAh[mt], &fBh[nt >> 1][(nt & 1) * 2]);
#pragma unroll
                for (int mt = 0; mt < 4; mt++)
#pragma unroll
                    for (int nt = 0; nt < 4; nt++)
                        mmaB(acc[mt][nt], fAh[mt], &fBl[nt >> 1][(nt & 1) * 2]);
#pragma unroll
                for (int mt = 0; mt < 4; mt++)
#pragma unroll
                    for (int nt = 0; nt < 4; nt++)
                        mmaB(acc[mt][nt], fAl[mt], &fBh[nt >> 1][(nt & 1) * 2]);
            }
        }
        __syncthreads();
    }

    // epilogue
    const int rr = lane >> 2;
    const int cc2 = (lane & 3) * 2;
#pragma unroll
    for (int mt = 0; mt < 4; mt++) {
#pragma unroll
        for (int nt = 0; nt < 4; nt++) {
            int row0 = bm + wm + mt * 16 + rr;
            int col = bn + wn + nt * 8 + cc2;
            float cb0 = cBias ? cBias[col] : 0.f;
            float cb1 = cBias ? cBias[col + 1] : 0.f;
#pragma unroll
            for (int h = 0; h < 2; h++) {
                int row = row0 + h * 8;
                float rb = rBias ? rBias[row] : 0.f;
                float v0 = acc[mt][nt][h * 2 + 0] + rb + cb0;
                float v1 = acc[mt][nt][h * 2 + 1] + rb + cb1;
                long o = (long)bz * oS + (long)row * ldc + col;
                if (OUT == 0) {
                    *(float2*)(outF + o) = make_float2(v0, v1);
                } else if (OUT == 1) {
                    st_split2(oH + o, oL + o, v0, v1);
                } else {
                    __half* hp = reinterpret_cast<__half*>(oH);
                    *(half2*)(hp + o) = __floats2half2_rn(v0, v1);
                }
            }
        }
    }
}

// ---------------- elementwise kernels ----------------
// weight splits: seg0 gw->fp16 pair, seg1 tw->bf16 pair, seg2 pw->bf16 pair, seg3 ww->fp16 pair
__global__ void __launch_bounds__(256) split_w4(
    const float* __restrict__ w0, const float* __restrict__ w1,
    const float* __restrict__ w2, const float* __restrict__ w3,
    __half* __restrict__ gh, __half* __restrict__ gl,
    bf16* __restrict__ th, bf16* __restrict__ tl,
    bf16* __restrict__ ph, bf16* __restrict__ pl,
    __half* __restrict__ wh, __half* __restrict__ wl)
{
    const int seg = blockIdx.x >> 11;
    const int i = (blockIdx.x & 2047) * 256 + threadIdx.x;
    if (seg == 0 || seg == 3) {
        const float* w = seg == 0 ? w0 : w3;
        __half* hi = seg == 0 ? gh : wh;
        __half* lo = seg == 0 ? gl : wl;
        float v = w[i];
        __half h = __float2half_rn(v);
        hi[i] = h;
        lo[i] = __float2half_rn(v - __half2float(h));
    } else {
        const float* w = seg == 1 ? w1 : w2;
        bf16* hi = seg == 1 ? th : ph;
        bf16* lo = seg == 1 ? tl : pl;
        float v = w[i];
        bf16 h = __float2bfloat16(v);
        hi[i] = h;
        lo[i] = __float2bfloat16(v - __bfloat162float(h));
    }
}

// x (b,c,n) -> xT (b,n,c): bf16 hi/lo + single fp16
__global__ void __launch_bounds__(256) xpose_split(const float* __restrict__ x,
                                                   bf16* __restrict__ hi, bf16* __restrict__ lo,
                                                   __half* __restrict__ xf)
{
    __shared__ float t[32][33];
    const int b = blockIdx.z, n0 = blockIdx.x * 32, c0 = blockIdx.y * 32;
    const int tx = threadIdx.x & 31, ty = threadIdx.x >> 5;
#pragma unroll
    for (int i = 0; i < 4; i++) {
        int r = ty + i * 8;
        t[r][tx] = x[((long)b * CC + c0 + r) * NT + n0 + tx];
    }
    __syncthreads();
#pragma unroll
    for (int i = 0; i < 4; i++) {
        int r = ty + i * 8;
        float v = t[tx][r];
        long o = ((long)b * NT + n0 + r) * CC + c0 + tx;
        bf16 h = __float2bfloat16(v);
        hi[o] = h;
        lo[o] = __float2bfloat16(v - __bfloat162float(h));
        xf[o] = __float2half_rn(v);
    }
}

__global__ void __launch_bounds__(256) softmax_split(const float* __restrict__ f,
                                                     __half* __restrict__ hi, __half* __restrict__ lo)
{
    const float4* pv = (const float4*)(f + (size_t)blockIdx.x * NT);
    const int tid = threadIdx.x;
    float4 a = pv[tid], b = pv[tid + 256];
    float m = fmaxf(fmaxf(fmaxf(a.x, a.y), fmaxf(a.z, a.w)),
                    fmaxf(fmaxf(b.x, b.y), fmaxf(b.z, b.w)));
    __shared__ float red[8];
#pragma unroll
    for (int o = 16; o > 0; o >>= 1) m = fmaxf(m, __shfl_xor_sync(~0u, m, o));
    if ((tid & 31) == 0) red[tid >> 5] = m;
    __syncthreads();
    float mm = red[0];
#pragma unroll
    for (int i = 1; i < 8; i++) mm = fmaxf(mm, red[i]);
    __syncthreads();
    a.x = expf(a.x - mm); a.y = expf(a.y - mm); a.z = expf(a.z - mm); a.w = expf(a.w - mm);
    b.x = expf(b.x - mm); b.y = expf(b.y - mm); b.z = expf(b.z - mm); b.w = expf(b.w - mm);
    float s = (a.x + a.y) + (a.z + a.w) + (b.x + b.y) + (b.z + b.w);
#pragma unroll
    for (int o = 16; o > 0; o >>= 1) s += __shfl_xor_sync(~0u, s, o);
    if ((tid & 31) == 0) red[tid >> 5] = s;
    __syncthreads();
    float sum = 0.f;
#pragma unroll
    for (int i = 0; i < 8; i++) sum += red[i];
    float inv = 1.0f / sum;
    size_t off = (size_t)blockIdx.x * NT;
    st_splitH2(hi + off + tid * 4, lo + off + tid * 4, a.x * inv, a.y * inv);
    st_splitH2(hi + off + tid * 4 + 2, lo + off + tid * 4 + 2, a.z * inv, a.w * inv);
    st_splitH2(hi + off + 1024 + tid * 4, lo + off + 1024 + tid * 4, b.x * inv, b.y * inv);
    st_splitH2(hi + off + 1024 + tid * 4 + 2, lo + off + 1024 + tid * 4 + 2, b.z * inv, b.w * inv);
}

__global__ void __launch_bounds__(256)
bn_residual(const float* __restrict__ wy, const float* __restrict__ x,
            const float* __restrict__ gamma, const float* __restrict__ beta,
            float* __restrict__ out)
{
    const int c = blockIdx.x, tid = threadIdx.x;
    float vals[32], s = 0.f, ss = 0.f;
#pragma unroll
    for (int b = 0; b < BB; b++) {
        const float* p = wy + ((size_t)b * CC + c) * NT;
#pragma unroll
        for (int j = 0; j < 8; j++) {
            float v = p[tid + j * 256];
            vals[b * 8 + j] = v; s += v; ss += v * v;
        }
    }
    __shared__ float r1[8], r2[8];
#pragma unroll
    for (int o = 16; o > 0; o >>= 1) {
        s += __shfl_xor_sync(~0u, s, o);
        ss += __shfl_xor_sync(~0u, ss, o);
    }
    if ((tid & 31) == 0) { r1[tid >> 5] = s; r2[tid >> 5] = ss; }
    __syncthreads();
    s = 0.f; ss = 0.f;
#pragma unroll
    for (int i = 0; i < 8; i++) { s += r1[i]; ss += r2[i]; }
    const float cnt = (float)(BB * NT);
    float mean = s / cnt;
    float var = ss / cnt - mean * mean;
    float scale = rsqrtf(var + 1e-5f) * gamma[c];
    float shift = beta[c] - mean * scale;
#pragma unroll
    for (int b = 0; b < BB; b++) {
        size_t off = ((size_t)b * CC + c) * NT;
#pragma unroll
        for (int j = 0; j < 8; j++) {
            int n = tid + j * 256;
            out[off + n] = vals[b * 8 + j] * scale + shift + x[off + n];
        }
    }
}

// ---------------------------------------------------------------------------
extern "C" void kernel_launch(void* const* d_in, const int* in_sizes, int n_in,
                              void* d_out, int out_size)
{
    const float* x   = (const float*)d_in[0];
    const float* gw  = (const float*)d_in[1];
    const float* gb  = (const float*)d_in[2];
    const float* tw  = (const float*)d_in[3];
    const float* tb  = (const float*)d_in[4];
    const float* pw  = (const float*)d_in[5];
    const float* pb  = (const float*)d_in[6];
    const float* ww  = (const float*)d_in[7];
    const float* wb  = (const float*)d_in[8];
    const float* bg  = (const float*)d_in[9];
    const float* bbt = (const float*)d_in[10];
    float* out = (float*)d_out;

    bf16 *xTh, *xTl, *wth, *wtl, *wph, *wpl, *thh, *thl, *phh, *phl;
    __half *xTf, *wgh, *wgl, *wwh, *wwl, *gs, *ath, *atl, *yv;
    float *ff, *wy;
    cudaGetSymbolAddress((void**)&xTh, s_xT_h); cudaGetSymbolAddress((void**)&xTl, s_xT_l);
    cudaGetSymbolAddress((void**)&xTf, s_xT_f);
    cudaGetSymbolAddress((void**)&wth, s_wt_h); cudaGetSymbolAddress((void**)&wtl, s_wt_l);
    cudaGetSymbolAddress((void**)&wph, s_wp_h); cudaGetSymbolAddress((void**)&wpl, s_wp_l);
    cudaGetSymbolAddress((void**)&wgh, s_wgH);  cudaGetSymbolAddress((void**)&wgl, s_wgL);
    cudaGetSymbolAddress((void**)&wwh, s_wwH);  cudaGetSymbolAddress((void**)&wwl, s_wwL);
    cudaGetSymbolAddress((void**)&thh, s_th_h); cudaGetSymbolAddress((void**)&thl, s_th_l);
    cudaGetSymbolAddress((void**)&phh, s_ph_h); cudaGetSymbolAddress((void**)&phl, s_ph_l);
    cudaGetSymbolAddress((void**)&gs,  s_gs);
    cudaGetSymbolAddress((void**)&ath, s_atH);  cudaGetSymbolAddress((void**)&atl, s_atL);
    cudaGetSymbolAddress((void**)&yv,  s_y);
    cudaGetSymbolAddress((void**)&ff,  s_f);    cudaGetSymbolAddress((void**)&wy,  s_wy);

    cudaFuncSetAttribute(gemm_tc<0, 0>, cudaFuncAttributeMaxDynamicSharedMemorySize, SMEM_BF);
    cudaFuncSetAttribute(gemm_tc<1, 0>, cudaFuncAttributeMaxDynamicSharedMemorySize, SMEM_BF);
    cudaFuncSetAttribute(gemm_tc<0, 1>, cudaFuncAttributeMaxDynamicSharedMemorySize, SMEM_F16);
    cudaFuncSetAttribute(gemm_tc<2, 1>, cudaFuncAttributeMaxDynamicSharedMemorySize, SMEM_F16);

    split_w4<<<4 * 2048, 256>>>(gw, tw, pw, ww,
                                wgh, wgl, wth, wtl, wph, wpl, wwh, wwl);
    xpose_split<<<dim3(NT / 32, CC / 32, BB), 256>>>(x, xTh, xTl, xTf);

    const long sXT = (long)NT * CC, sPR = (long)NT * CIN;
    const long sGS = (long)CIN * NT, sAT = (long)NT * NT, sWY = (long)CC * NT;

    // theta + phi fused (bf16 3-prod): rows=NT cols=CIN K=CC, z in [0,8)
    gemm_tc<1, 0><<<dim3(CIN / 128, NT / 128, 2 * BB), 256, SMEM_BF>>>(
        xTh, xTl, sXT, CC, wth, wtl, 0, CC, nullptr, thh, thl, sPR, CIN, nullptr, tb, CC,
        wph, wpl, pb, phh, phl);
    // g (fp16 2-prod): rows=CIN (o), cols=NT (m), K=CC; out single fp16 [o,m], rBias=g_b
    gemm_tc<2, 1><<<dim3(NT / 128, CIN / 128, BB), 256, SMEM_F16>>>(
        (const bf16*)wgh, (const bf16*)wgl, 0, CC, (const bf16*)xTf, nullptr, sXT, CC,
        nullptr, (bf16*)gs, nullptr, sGS, NT, gb, nullptr, CC,
        nullptr, nullptr, nullptr, nullptr, nullptr);
    // f (bf16 3-prod): rows=NT cols=NT K=CIN, out fp32
    gemm_tc<0, 0><<<dim3(NT / 128, NT / 128, BB), 256, SMEM_BF>>>(
        thh, thl, sPR, CIN, phh, phl, sPR, CIN, ff, nullptr, nullptr, sAT, NT, nullptr, nullptr, CIN,
        nullptr, nullptr, nullptr, nullptr, nullptr);
    // softmax -> fp16 split attn
    softmax_split<<<BB * NT, 256>>>(ff, ath, atl);
    // y (fp16 2-prod): rows=NT (n), cols=CIN (o), K=NT; A=attn 2-limb, B=g 1-limb; out fp16 [n,o]
    gemm_tc<2, 1><<<dim3(CIN / 128, NT / 128, BB), 256, SMEM_F16>>>(
        (const bf16*)ath, (const bf16*)atl, sAT, NT, (const bf16*)gs, nullptr, sGS, NT,
        nullptr, (bf16*)yv, nullptr, sPR, CIN, nullptr, nullptr, NT,
        nullptr, nullptr, nullptr, nullptr, nullptr);
    // w_y (fp16 2-prod): rows=CC (c), cols=NT (n), K=CIN; A=ww 2-limb, B=y 1-limb; out fp32 + wb
    gemm_tc<0, 1><<<dim3(NT / 128, CC / 128, BB), 256, SMEM_F16>>>(
        (const bf16*)wwh, (const bf16*)wwl, 0, CIN, (const bf16*)yv, nullptr, sPR, CIN,
        wy, nullptr, nullptr, sWY, NT, wb, nullptr, CIN,
        nullptr, nullptr, nullptr, nullptr, nullptr);
    // BN + residual
    bn_residual<<<CC, 256>>>(wy, x, bg, bbt, out);
}

// round 11
// speedup vs baseline: 1.4365x; 1.1882x over previous
#include <cuda_runtime.h>
#include <cuda_bf16.h>
#include <cuda_fp16.h>
#include <cstdint>

typedef __nv_bfloat16 bf16;

#define BB 4
#define CC 1024
#define CIN 512
#define NT 2048

// ---------------- static scratch ----------------
// logit path (bf16 2-limb)
__device__ __align__(256) bf16 s_xT_h[BB * NT * CC];
__device__ __align__(256) bf16 s_xT_l[BB * NT * CC];
__device__ __align__(256) bf16 s_wt_h[CIN * CC], s_wt_l[CIN * CC];
__device__ __align__(256) bf16 s_wp_h[CIN * CC], s_wp_l[CIN * CC];
__device__ __align__(256) bf16 s_th_h[BB * NT * CIN], s_th_l[BB * NT * CIN];
__device__ __align__(256) bf16 s_ph_h[BB * NT * CIN], s_ph_l[BB * NT * CIN];
__device__ __align__(256) float s_f[BB * NT * NT];
// value path (single-limb fp16)
__device__ __align__(256) __half s_xT_f[BB * NT * CC];
__device__ __align__(256) __half s_wgF[CIN * CC];
__device__ __align__(256) __half s_wwF[CC * CIN];
__device__ __align__(256) __half s_gs[BB * CIN * NT];   // g (b,o,m)
__device__ __align__(256) __half s_at[BB * NT * NT];    // attn (b,n,m)
__device__ __align__(256) __half s_y[BB * NT * CIN];    // y (b,n,o)
__device__ __align__(256) float s_wy[BB * CC * NT];

// ---------------- helpers ----------------
__device__ __forceinline__ uint32_t smem_u32(const void* p) {
    uint32_t a;
    asm("{ .reg .u64 t; cvta.to.shared.u64 t, %1; cvt.u32.u64 %0, t; }" : "=r"(a) : "l"(p));
    return a;
}
__device__ __forceinline__ void st_split2(bf16* hi, bf16* lo, float v0, float v1) {
    bf16 h0 = __float2bfloat16(v0), h1 = __float2bfloat16(v1);
    *(uint32_t*)hi = (uint32_t)__bfloat16_as_ushort(h0) |
                     ((uint32_t)__bfloat16_as_ushort(h1) << 16);
    bf16 l0 = __float2bfloat16(v0 - __bfloat162float(h0));
    bf16 l1 = __float2bfloat16(v1 - __bfloat162float(h1));
    *(uint32_t*)lo = (uint32_t)__bfloat16_as_ushort(l0) |
                     ((uint32_t)__bfloat16_as_ushort(l1) << 16);
}

// ---------------- HMMA GEMM ----------------
// MODE 0: bf16, A 2-limb, B 2-limb, 3 products (HH+HL+LH)
// MODE 1: fp16, A 1-limb, B 1-limb, 1 product
// CTA tile 128x128, K-chunk 32, 8 warps, warp tile 64x32, 3-stage cp.async, 2 CTA/SM.
#define NSTG 3
#define TILE_B 8192
#define SMEM_BF (NSTG * 4 * TILE_B)   // 96 KB
#define SMEM_H1 (NSTG * 2 * TILE_B)   // 48 KB

__device__ __forceinline__ uint32_t sw_off(int row, int kv) {
    return (uint32_t)(row * 64 + ((kv ^ ((row >> 1) & 3)) << 4));
}
__device__ __forceinline__ void cpa_tile(uint32_t sdst, const bf16* __restrict__ g,
                                         int ld, int k0, int tid) {
#pragma unroll
    for (int i = 0; i < 2; i++) {
        int idx = tid + i * 256;
        int row = idx >> 2;
        int kv  = idx & 3;
        uint32_t dst = sdst + sw_off(row, kv);
        const void* src = g + (long)row * ld + k0 + kv * 8;
        asm volatile("cp.async.cg.shared.global [%0], [%1], 16;" :: "r"(dst), "l"(src));
    }
}
__device__ __forceinline__ void ldmA(uint32_t* r, uint32_t base, int m0, int k16, int lane) {
    int m = m0 + (lane & 15);
    int kv = k16 * 2 + (lane >> 4);
    uint32_t addr = base + sw_off(m, kv);
    asm volatile("ldmatrix.sync.aligned.m8n8.x4.shared.b16 {%0,%1,%2,%3}, [%4];"
                 : "=r"(r[0]), "=r"(r[1]), "=r"(r[2]), "=r"(r[3]) : "r"(addr));
}
__device__ __forceinline__ void ldmB(uint32_t* r, uint32_t base, int n0, int k16, int lane) {
    int row = n0 + (lane & 7) + ((lane >> 4) << 3);
    int kv = k16 * 2 + ((lane >> 3) & 1);
    uint32_t addr = base + sw_off(row, kv);
    asm volatile("ldmatrix.sync.aligned.m8n8.x4.shared.b16 {%0,%1,%2,%3}, [%4];"
                 : "=r"(r[0]), "=r"(r[1]), "=r"(r[2]), "=r"(r[3]) : "r"(addr));
}
__device__ __forceinline__ void mmaB(float* c, const uint32_t* a, const uint32_t* b) {
    asm volatile(
        "mma.sync.aligned.m16n8k16.row.col.f32.bf16.bf16.f32 "
        "{%0,%1,%2,%3},{%4,%5,%6,%7},{%8,%9},{%0,%1,%2,%3};"
        : "+f"(c[0]), "+f"(c[1]), "+f"(c[2]), "+f"(c[3])
        : "r"(a[0]), "r"(a[1]), "r"(a[2]), "r"(a[3]), "r"(b[0]), "r"(b[1]));
}
__device__ __forceinline__ void mmaH(float* c, const uint32_t* a, const uint32_t* b) {
    asm volatile(
        "mma.sync.aligned.m16n8k16.row.col.f32.f16.f16.f32 "
        "{%0,%1,%2,%3},{%4,%5,%6,%7},{%8,%9},{%0,%1,%2,%3};"
        : "+f"(c[0]), "+f"(c[1]), "+f"(c[2]), "+f"(c[3])
        : "r"(a[0]), "r"(a[1]), "r"(a[2]), "r"(a[3]), "r"(b[0]), "r"(b[1]));
}

// OUT: 0 = fp32 (+rBias,+cBias), 1 = split bf16 (+biases), 2 = single fp16 (+rBias)
template <int OUT, int MODE>
__global__ void __launch_bounds__(256, 2)
gemm_tc(const bf16* __restrict__ aH, const bf16* __restrict__ aL, long aS, int lda,
        const bf16* __restrict__ bH, const bf16* __restrict__ bL, long bS, int ldb,
        float* __restrict__ outF, bf16* __restrict__ oH, bf16* __restrict__ oL,
        long oS, int ldc, const float* __restrict__ rBias,
        const float* __restrict__ cBias, int K,
        const bf16* __restrict__ bH2, const bf16* __restrict__ bL2,
        const float* __restrict__ cBias2,
        bf16* __restrict__ oH2, bf16* __restrict__ oL2)
{
    constexpr int NTILE = (MODE == 0) ? 4 : 2;
    constexpr int STGB = NTILE * TILE_B;
    extern __shared__ char smraw[];
    const uint32_t sb = smem_u32(smraw);

    const int tid = threadIdx.x, wid = tid >> 5, lane = tid & 31;
    const int bn = blockIdx.x * 128, bm = blockIdx.y * 128;
    int bz = blockIdx.z;
    if (bH2 && bz >= BB) {
        bz -= BB;
        bH = bH2; bL = bL2; cBias = cBias2; oH = oH2; oL = oL2;
    }
    const int wm = (wid >> 2) * 64;
    const int wn = (wid & 3) * 32;

    const bf16* A0 = aH + (long)bz * aS + (long)bm * lda;
    const bf16* A1 = (MODE == 0) ? aL + (long)bz * aS + (long)bm * lda : nullptr;
    const bf16* B0 = bH + (long)bz * bS + (long)bn * ldb;
    const bf16* B1 = (MODE == 0) ? bL + (long)bz * bS + (long)bn * ldb : nullptr;
    const int nch = K >> 5;

    float acc[4][4][4];
#pragma unroll
    for (int i = 0; i < 4; i++)
#pragma unroll
        for (int j = 0; j < 4; j++)
#pragma unroll
            for (int e = 0; e < 4; e++) acc[i][j][e] = 0.f;

#pragma unroll
    for (int s = 0; s < NSTG - 1; s++) {
        uint32_t st = sb + s * STGB;
        int k0 = s << 5;
        if (MODE == 0) {
            cpa_tile(st,              A0, lda, k0, tid);
            cpa_tile(st + TILE_B,     A1, lda, k0, tid);
            cpa_tile(st + 2 * TILE_B, B0, ldb, k0, tid);
            cpa_tile(st + 3 * TILE_B, B1, ldb, k0, tid);
        } else {
            cpa_tile(st,          A0, lda, k0, tid);
            cpa_tile(st + TILE_B, B0, ldb, k0, tid);
        }
        asm volatile("cp.async.commit_group;");
    }

    for (int c = 0; c < nch; c++) {
        asm volatile("cp.async.wait_group 1;");
        __syncthreads();
        if (c + NSTG - 1 < nch) {
            uint32_t st = sb + ((c + NSTG - 1) % NSTG) * STGB;
            int k0 = (c + NSTG - 1) << 5;
            if (MODE == 0) {
                cpa_tile(st,              A0, lda, k0, tid);
                cpa_tile(st + TILE_B,     A1, lda, k0, tid);
                cpa_tile(st + 2 * TILE_B, B0, ldb, k0, tid);
                cpa_tile(st + 3 * TILE_B, B1, ldb, k0, tid);
            } else {
                cpa_tile(st,          A0, lda, k0, tid);
                cpa_tile(st + TILE_B, B0, ldb, k0, tid);
            }
        }
        asm volatile("cp.async.commit_group;");

        const uint32_t st = sb + (c % NSTG) * STGB;
#pragma unroll
        for (int k16 = 0; k16 < 2; k16++) {
            if (MODE == 1) {
                uint32_t fA[4][4], fB[2][4];
#pragma unroll
                for (int mt = 0; mt < 4; mt++)
                    ldmA(fA[mt], st, wm + mt * 16, k16, lane);
                ldmB(fB[0], st + TILE_B, wn,      k16, lane);
                ldmB(fB[1], st + TILE_B, wn + 16, k16, lane);
#pragma unroll
                for (int mt = 0; mt < 4; mt++)
#pragma unroll
                    for (int nt = 0; nt < 4; nt++)
                        mmaH(acc[mt][nt], fA[mt], &fB[nt >> 1][(nt & 1) * 2]);
            } else {
                uint32_t fAh[4][4], fAl[4][4], fBh[2][4], fBl[2][4];
#pragma unroll
                for (int mt = 0; mt < 4; mt++) {
                    ldmA(fAh[mt], st,          wm + mt * 16, k16, lane);
                    ldmA(fAl[mt], st + TILE_B, wm + mt * 16, k16, lane);
                }
                ldmB(fBh[0], st + 2 * TILE_B, wn,      k16, lane);
                ldmB(fBh[1], st + 2 * TILE_B, wn + 16, k16, lane);
                ldmB(fBl[0], st + 3 * TILE_B, wn,      k16, lane);
                ldmB(fBl[1], st + 3 * TILE_B, wn + 16, k16, lane);
#pragma unroll
                for (int mt = 0; mt < 4; mt++)
#pragma unroll
                    for (int nt = 0; nt < 4; nt++)
                        mmaB(acc[mt][nt], fAh[mt], &fBh[nt >> 1][(nt & 1) * 2]);
#pragma unroll
                for (int mt = 0; mt < 4; mt++)
#pragma unroll
                    for (int nt = 0; nt < 4; nt++)
                        mmaB(acc[mt][nt], fAh[mt], &fBl[nt >> 1][(nt & 1) * 2]);
#pragma unroll
                for (int mt = 0; mt < 4; mt++)
#pragma unroll
                    for (int nt = 0; nt < 4; nt++)
                        mmaB(acc[mt][nt], fAl[mt], &fBh[nt >> 1][(nt & 1) * 2]);
            }
        }
        __syncthreads();
    }

    // epilogue
    const int rr = lane >> 2;
    const int cc2 = (lane & 3) * 2;
#pragma unroll
    for (int mt = 0; mt < 4; mt++) {
#pragma unroll
        for (int nt = 0; nt < 4; nt++) {
            int row0 = bm + wm + mt * 16 + rr;
            int col = bn + wn + nt * 8 + cc2;
            float cb0 = cBias ? cBias[col] : 0.f;
            float cb1 = cBias ? cBias[col + 1] : 0.f;
#pragma unroll
            for (int h = 0; h < 2; h++) {
                int row = row0 + h * 8;
                float rb = rBias ? rBias[row] : 0.f;
                float v0 = acc[mt][nt][h * 2 + 0] + rb + cb0;
                float v1 = acc[mt][nt][h * 2 + 1] + rb + cb1;
                long o = (long)bz * oS + (long)row * ldc + col;
                if (OUT == 0) {
                    *(float2*)(outF + o) = make_float2(v0, v1);
                } else if (OUT == 1) {
                    st_split2(oH + o, oL + o, v0, v1);
                } else {
                    __half* hp = reinterpret_cast<__half*>(oH);
                    *(half2*)(hp + o) = __floats2half2_rn(v0, v1);
                }
            }
        }
    }
}

// ---------------- elementwise kernels ----------------
// seg0: gw -> fp16 single; seg1: tw -> bf16 pair; seg2: pw -> bf16 pair; seg3: ww -> fp16 single
__global__ void __launch_bounds__(256) split_w4(
    const float* __restrict__ w0, const float* __restrict__ w1,
    const float* __restrict__ w2, const float* __restrict__ w3,
    __half* __restrict__ gf,
    bf16* __restrict__ th, bf16* __restrict__ tl,
    bf16* __restrict__ ph, bf16* __restrict__ pl,
    __half* __restrict__ wf)
{
    const int seg = blockIdx.x >> 11;
    const int i = (blockIdx.x & 2047) * 256 + threadIdx.x;
    if (seg == 0) {
        gf[i] = __float2half_rn(w0[i]);
    } else if (seg == 3) {
        wf[i] = __float2half_rn(w3[i]);
    } else {
        const float* w = seg == 1 ? w1 : w2;
        bf16* hi = seg == 1 ? th : ph;
        bf16* lo = seg == 1 ? tl : pl;
        float v = w[i];
        bf16 h = __float2bfloat16(v);
        hi[i] = h;
        lo[i] = __float2bfloat16(v - __bfloat162float(h));
    }
}

// x (b,c,n) -> xT (b,n,c): bf16 hi/lo + single fp16
__global__ void __launch_bounds__(256) xpose_split(const float* __restrict__ x,
                                                   bf16* __restrict__ hi, bf16* __restrict__ lo,
                                                   __half* __restrict__ xf)
{
    __shared__ float t[32][33];
    const int b = blockIdx.z, n0 = blockIdx.x * 32, c0 = blockIdx.y * 32;
    const int tx = threadIdx.x & 31, ty = threadIdx.x >> 5;
#pragma unroll
    for (int i = 0; i < 4; i++) {
        int r = ty + i * 8;
        t[r][tx] = x[((long)b * CC + c0 + r) * NT + n0 + tx];
    }
    __syncthreads();
#pragma unroll
    for (int i = 0; i < 4; i++) {
        int r = ty + i * 8;
        float v = t[tx][r];
        long o = ((long)b * NT + n0 + r) * CC + c0 + tx;
        bf16 h = __float2bfloat16(v);
        hi[o] = h;
        lo[o] = __float2bfloat16(v - __bfloat162float(h));
        xf[o] = __float2half_rn(v);
    }
}

__global__ void __launch_bounds__(256) softmax_h(const float* __restrict__ f,
                                                 __half* __restrict__ at)
{
    const float4* pv = (const float4*)(f + (size_t)blockIdx.x * NT);
    const int tid = threadIdx.x;
    float4 a = pv[tid], b = pv[tid + 256];
    float m = fmaxf(fmaxf(fmaxf(a.x, a.y), fmaxf(a.z, a.w)),
                    fmaxf(fmaxf(b.x, b.y), fmaxf(b.z, b.w)));
    __shared__ float red[8];
#pragma unroll
    for (int o = 16; o > 0; o >>= 1) m = fmaxf(m, __shfl_xor_sync(~0u, m, o));
    if ((tid & 31) == 0) red[tid >> 5] = m;
    __syncthreads();
    float mm = red[0];
#pragma unroll
    for (int i = 1; i < 8; i++) mm = fmaxf(mm, red[i]);
    __syncthreads();
    a.x = expf(a.x - mm); a.y = expf(a.y - mm); a.z = expf(a.z - mm); a.w = expf(a.w - mm);
    b.x = expf(b.x - mm); b.y = expf(b.y - mm); b.z = expf(b.z - mm); b.w = expf(b.w - mm);
    float s = (a.x + a.y) + (a.z + a.w) + (b.x + b.y) + (b.z + b.w);
#pragma unroll
    for (int o = 16; o > 0; o >>= 1) s += __shfl_xor_sync(~0u, s, o);
    if ((tid & 31) == 0) red[tid >> 5] = s;
    __syncthreads();
    float sum = 0.f;
#pragma unroll
    for (int i = 0; i < 8; i++) sum += red[i];
    float inv = 1.0f / sum;
    size_t off = (size_t)blockIdx.x * NT;
    *(half2*)(at + off + tid * 4)     = __floats2half2_rn(a.x * inv, a.y * inv);
    *(half2*)(at + off + tid * 4 + 2) = __floats2half2_rn(a.z * inv, a.w * inv);
    *(half2*)(at + off + 1024 + tid * 4)     = __floats2half2_rn(b.x * inv, b.y * inv);
    *(half2*)(at + off + 1024 + tid * 4 + 2) = __floats2half2_rn(b.z * inv, b.w * inv);
}

__global__ void __launch_bounds__(256)
bn_residual(const float* __restrict__ wy, const float* __restrict__ x,
            const float* __restrict__ gamma, const float* __restrict__ beta,
            float* __restrict__ out)
{
    const int c = blockIdx.x, tid = threadIdx.x;
    float vals[32], s = 0.f, ss = 0.f;
#pragma unroll
    for (int b = 0; b < BB; b++) {
        const float* p = wy + ((size_t)b * CC + c) * NT;
#pragma unroll
        for (int j = 0; j < 8; j++) {
            float v = p[tid + j * 256];
            vals[b * 8 + j] = v; s += v; ss += v * v;
        }
    }
    __shared__ float r1[8], r2[8];
#pragma unroll
    for (int o = 16; o > 0; o >>= 1) {
        s += __shfl_xor_sync(~0u, s, o);
        ss += __shfl_xor_sync(~0u, ss, o);
    }
    if ((tid & 31) == 0) { r1[tid >> 5] = s; r2[tid >> 5] = ss; }
    __syncthreads();
    s = 0.f; ss = 0.f;
#pragma unroll
    for (int i = 0; i < 8; i++) { s += r1[i]; ss += r2[i]; }
    const float cnt = (float)(BB * NT);
    float mean = s / cnt;
    float var = ss / cnt - mean * mean;
    float scale = rsqrtf(var + 1e-5f) * gamma[c];
    float shift = beta[c] - mean * scale;
#pragma unroll
    for (int b = 0; b < BB; b++) {
        size_t off = ((size_t)b * CC + c) * NT;
#pragma unroll
        for (int j = 0; j < 8; j++) {
            int n = tid + j * 256;
            out[off + n] = vals[b * 8 + j] * scale + shift + x[off + n];
        }
    }
}

// ---------------------------------------------------------------------------
extern "C" void kernel_launch(void* const* d_in, const int* in_sizes, int n_in,
                              void* d_out, int out_size)
{
    const float* x   = (const float*)d_in[0];
    const float* gw  = (const float*)d_in[1];
    const float* gb  = (const float*)d_in[2];
    const float* tw  = (const float*)d_in[3];
    const float* tb  = (const float*)d_in[4];
    const float* pw  = (const float*)d_in[5];
    const float* pb  = (const float*)d_in[6];
    const float* ww  = (const float*)d_in[7];
    const float* wb  = (const float*)d_in[8];
    const float* bg  = (const float*)d_in[9];
    const float* bbt = (const float*)d_in[10];
    float* out = (float*)d_out;

    bf16 *xTh, *xTl, *wth, *wtl, *wph, *wpl, *thh, *thl, *phh, *phl;
    __half *xTf, *wgf, *wwf, *gs, *at, *yv;
    float *ff, *wy;
    cudaGetSymbolAddress((void**)&xTh, s_xT_h); cudaGetSymbolAddress((void**)&xTl, s_xT_l);
    cudaGetSymbolAddress((void**)&xTf, s_xT_f);
    cudaGetSymbolAddress((void**)&wth, s_wt_h); cudaGetSymbolAddress((void**)&wtl, s_wt_l);
    cudaGetSymbolAddress((void**)&wph, s_wp_h); cudaGetSymbolAddress((void**)&wpl, s_wp_l);
    cudaGetSymbolAddress((void**)&wgf, s_wgF);  cudaGetSymbolAddress((void**)&wwf, s_wwF);
    cudaGetSymbolAddress((void**)&thh, s_th_h); cudaGetSymbolAddress((void**)&thl, s_th_l);
    cudaGetSymbolAddress((void**)&phh, s_ph_h); cudaGetSymbolAddress((void**)&phl, s_ph_l);
    cudaGetSymbolAddress((void**)&gs,  s_gs);   cudaGetSymbolAddress((void**)&at,  s_at);
    cudaGetSymbolAddress((void**)&yv,  s_y);
    cudaGetSymbolAddress((void**)&ff,  s_f);    cudaGetSymbolAddress((void**)&wy,  s_wy);

    cudaFuncSetAttribute(gemm_tc<0, 0>, cudaFuncAttributeMaxDynamicSharedMemorySize, SMEM_BF);
    cudaFuncSetAttribute(gemm_tc<1, 0>, cudaFuncAttributeMaxDynamicSharedMemorySize, SMEM_BF);
    cudaFuncSetAttribute(gemm_tc<0, 1>, cudaFuncAttributeMaxDynamicSharedMemorySize, SMEM_H1);
    cudaFuncSetAttribute(gemm_tc<2, 1>, cudaFuncAttributeMaxDynamicSharedMemorySize, SMEM_H1);

    split_w4<<<4 * 2048, 256>>>(gw, tw, pw, ww, wgf, wth, wtl, wph, wpl, wwf);
    xpose_split<<<dim3(NT / 32, CC / 32, BB), 256>>>(x, xTh, xTl, xTf);

    const long sXT = (long)NT * CC, sPR = (long)NT * CIN;
    const long sGS = (long)CIN * NT, sAT = (long)NT * NT, sWY = (long)CC * NT;

    // theta + phi fused (bf16 3-prod): rows=NT cols=CIN K=CC, z in [0,8)
    gemm_tc<1, 0><<<dim3(CIN / 128, NT / 128, 2 * BB), 256, SMEM_BF>>>(
        xTh, xTl, sXT, CC, wth, wtl, 0, CC, nullptr, thh, thl, sPR, CIN, nullptr, tb, CC,
        wph, wpl, pb, phh, phl);
    // g (fp16 1-prod): rows=CIN (o), cols=NT (m), K=CC; out fp16 [o,m], rBias=g_b
    gemm_tc<2, 1><<<dim3(NT / 128, CIN / 128, BB), 256, SMEM_H1>>>(
        (const bf16*)wgf, nullptr, 0, CC, (const bf16*)xTf, nullptr, sXT, CC,
        nullptr, (bf16*)gs, nullptr, sGS, NT, gb, nullptr, CC,
        nullptr, nullptr, nullptr, nullptr, nullptr);
    // f (bf16 3-prod): rows=NT cols=NT K=CIN, out fp32
    gemm_tc<0, 0><<<dim3(NT / 128, NT / 128, BB), 256, SMEM_BF>>>(
        thh, thl, sPR, CIN, phh, phl, sPR, CIN, ff, nullptr, nullptr, sAT, NT, nullptr, nullptr, CIN,
        nullptr, nullptr, nullptr, nullptr, nullptr);
    // softmax -> single fp16 attn
    softmax_h<<<BB * NT, 256>>>(ff, at);
    // y (fp16 1-prod): rows=NT (n), cols=CIN (o), K=NT; A=attn, B=g; out fp16 [n,o]
    gemm_tc<2, 1><<<dim3(CIN / 128, NT / 128, BB), 256, SMEM_H1>>>(
        (const bf16*)at, nullptr, sAT, NT, (const bf16*)gs, nullptr, sGS, NT,
        nullptr, (bf16*)yv, nullptr, sPR, CIN, nullptr, nullptr, NT,
        nullptr, nullptr, nullptr, nullptr, nullptr);
    // w_y (fp16 1-prod): rows=CC (c), cols=NT (n), K=CIN; A=ww, B=y; out fp32 + wb
    gemm_tc<0, 1><<<dim3(NT / 128, CC / 128, BB), 256, SMEM_H1>>>(
        (const bf16*)wwf, nullptr, 0, CIN, (const bf16*)yv, nullptr, sPR, CIN,
        wy, nullptr, nullptr, sWY, NT, wb, nullptr, CIN,
        nullptr, nullptr, nullptr, nullptr, nullptr);
    // BN + residual
    bn_residual<<<CC, 256>>>(wy, x, bg, bbt, out);
}

// round 12
// speedup vs baseline: 1.5741x; 1.0958x over previous
#include <cuda_runtime.h>
#include <cuda_bf16.h>
#include <cuda_fp16.h>
#include <cstdint>

typedef __nv_bfloat16 bf16;

#define BB 4
#define CC 1024
#define CIN 512
#define NT 2048

// ---------------- static scratch ----------------
// logit path (bf16 2-limb)
__device__ __align__(256) bf16 s_xT_h[BB * NT * CC];
__device__ __align__(256) bf16 s_xT_l[BB * NT * CC];
__device__ __align__(256) bf16 s_wt_h[CIN * CC], s_wt_l[CIN * CC];
__device__ __align__(256) bf16 s_wp_h[CIN * CC], s_wp_l[CIN * CC];
__device__ __align__(256) bf16 s_th_h[BB * NT * CIN], s_th_l[BB * NT * CIN];
__device__ __align__(256) bf16 s_ph_h[BB * NT * CIN], s_ph_l[BB * NT * CIN];
__device__ __align__(256) float s_f[BB * NT * NT];
// value path (single-limb fp16)
__device__ __align__(256) __half s_xT_f[BB * NT * CC];
__device__ __align__(256) __half s_wgF[CIN * CC];
__device__ __align__(256) __half s_wwF[CC * CIN];
__device__ __align__(256) __half s_gs[BB * CIN * NT];   // g (b,o,m)
__device__ __align__(256) __half s_at[BB * NT * NT];    // attn (b,n,m)
__device__ __align__(256) __half s_y[BB * NT * CIN];    // y (b,n,o)
__device__ __align__(256) float s_wy[BB * CC * NT];

// ---------------- helpers ----------------
__device__ __forceinline__ uint32_t smem_u32(const void* p) {
    uint32_t a;
    asm("{ .reg .u64 t; cvta.to.shared.u64 t, %1; cvt.u32.u64 %0, t; }" : "=r"(a) : "l"(p));
    return a;
}
__device__ __forceinline__ void st_split2(bf16* hi, bf16* lo, float v0, float v1) {
    bf16 h0 = __float2bfloat16(v0), h1 = __float2bfloat16(v1);
    *(uint32_t*)hi = (uint32_t)__bfloat16_as_ushort(h0) |
                     ((uint32_t)__bfloat16_as_ushort(h1) << 16);
    bf16 l0 = __float2bfloat16(v0 - __bfloat162float(h0));
    bf16 l1 = __float2bfloat16(v1 - __bfloat162float(h1));
    *(uint32_t*)lo = (uint32_t)__bfloat16_as_ushort(l0) |
                     ((uint32_t)__bfloat16_as_ushort(l1) << 16);
}

// ---------------- HMMA GEMM ----------------
// MODE 0: bf16, A 2-limb, B 2-limb, 3 products (HH+LH+HL)
// MODE 1: fp16, A 1-limb, B 1-limb, 1 product
// CTA tile 128x128, 4 warps (2x2) of 64x64, K-chunk 32, 3-stage cp.async, 2 CTA/SM.
// 64x64 warp tiles halve LDSM bytes per flop vs 64x32 (smem crossbar is the wall).
#define NSTG 3
#define TILE_B 8192
#define SMEM_BF (NSTG * 4 * TILE_B)   // 96 KB
#define SMEM_H1 (NSTG * 2 * TILE_B)   // 48 KB

__device__ __forceinline__ uint32_t sw_off(int row, int kv) {
    return (uint32_t)(row * 64 + ((kv ^ ((row >> 1) & 3)) << 4));
}
__device__ __forceinline__ void cpa_tile(uint32_t sdst, const bf16* __restrict__ g,
                                         int ld, int k0, int tid) {
#pragma unroll
    for (int i = 0; i < 4; i++) {
        int idx = tid + i * 128;       // 0..511
        int row = idx >> 2;            // 0..127
        int kv  = idx & 3;
        uint32_t dst = sdst + sw_off(row, kv);
        const void* src = g + (long)row * ld + k0 + kv * 8;
        asm volatile("cp.async.cg.shared.global [%0], [%1], 16;" :: "r"(dst), "l"(src));
    }
}
__device__ __forceinline__ void ldmA(uint32_t* r, uint32_t base, int m0, int k16, int lane) {
    int m = m0 + (lane & 15);
    int kv = k16 * 2 + (lane >> 4);
    uint32_t addr = base + sw_off(m, kv);
    asm volatile("ldmatrix.sync.aligned.m8n8.x4.shared.b16 {%0,%1,%2,%3}, [%4];"
                 : "=r"(r[0]), "=r"(r[1]), "=r"(r[2]), "=r"(r[3]) : "r"(addr));
}
__device__ __forceinline__ void ldmB(uint32_t* r, uint32_t base, int n0, int k16, int lane) {
    int row = n0 + (lane & 7) + ((lane >> 4) << 3);
    int kv = k16 * 2 + ((lane >> 3) & 1);
    uint32_t addr = base + sw_off(row, kv);
    asm volatile("ldmatrix.sync.aligned.m8n8.x4.shared.b16 {%0,%1,%2,%3}, [%4];"
                 : "=r"(r[0]), "=r"(r[1]), "=r"(r[2]), "=r"(r[3]) : "r"(addr));
}
__device__ __forceinline__ void mmaB(float* c, const uint32_t* a, const uint32_t* b) {
    asm volatile(
        "mma.sync.aligned.m16n8k16.row.col.f32.bf16.bf16.f32 "
        "{%0,%1,%2,%3},{%4,%5,%6,%7},{%8,%9},{%0,%1,%2,%3};"
        : "+f"(c[0]), "+f"(c[1]), "+f"(c[2]), "+f"(c[3])
        : "r"(a[0]), "r"(a[1]), "r"(a[2]), "r"(a[3]), "r"(b[0]), "r"(b[1]));
}
__device__ __forceinline__ void mmaH(float* c, const uint32_t* a, const uint32_t* b) {
    asm volatile(
        "mma.sync.aligned.m16n8k16.row.col.f32.f16.f16.f32 "
        "{%0,%1,%2,%3},{%4,%5,%6,%7},{%8,%9},{%0,%1,%2,%3};"
        : "+f"(c[0]), "+f"(c[1]), "+f"(c[2]), "+f"(c[3])
        : "r"(a[0]), "r"(a[1]), "r"(a[2]), "r"(a[3]), "r"(b[0]), "r"(b[1]));
}

// OUT: 0 = fp32 (+rBias,+cBias), 1 = split bf16 (+biases), 2 = single fp16 (+rBias)
template <int OUT, int MODE>
__global__ void __launch_bounds__(128, 2)
gemm_tc(const bf16* __restrict__ aH, const bf16* __restrict__ aL, long aS, int lda,
        const bf16* __restrict__ bH, const bf16* __restrict__ bL, long bS, int ldb,
        float* __restrict__ outF, bf16* __restrict__ oH, bf16* __restrict__ oL,
        long oS, int ldc, const float* __restrict__ rBias,
        const float* __restrict__ cBias, int K,
        const bf16* __restrict__ bH2, const bf16* __restrict__ bL2,
        const float* __restrict__ cBias2,
        bf16* __restrict__ oH2, bf16* __restrict__ oL2)
{
    constexpr int NTILE = (MODE == 0) ? 4 : 2;
    constexpr int STGB = NTILE * TILE_B;
    extern __shared__ char smraw[];
    const uint32_t sb = smem_u32(smraw);

    const int tid = threadIdx.x, wid = tid >> 5, lane = tid & 31;
    const int bn = blockIdx.x * 128, bm = blockIdx.y * 128;
    int bz = blockIdx.z;
    if (bH2 && bz >= BB) {
        bz -= BB;
        bH = bH2; bL = bL2; cBias = cBias2; oH = oH2; oL = oL2;
    }
    const int wm = (wid & 1) * 64;     // 0,64
    const int wn = (wid >> 1) * 64;    // 0,64

    const bf16* A0 = aH + (long)bz * aS + (long)bm * lda;
    const bf16* A1 = (MODE == 0) ? aL + (long)bz * aS + (long)bm * lda : nullptr;
    const bf16* B0 = bH + (long)bz * bS + (long)bn * ldb;
    const bf16* B1 = (MODE == 0) ? bL + (long)bz * bS + (long)bn * ldb : nullptr;
    const int nch = K >> 5;

    float acc[4][8][4];
#pragma unroll
    for (int i = 0; i < 4; i++)
#pragma unroll
        for (int j = 0; j < 8; j++)
#pragma unroll
            for (int e = 0; e < 4; e++) acc[i][j][e] = 0.f;

#pragma unroll
    for (int s = 0; s < NSTG - 1; s++) {
        uint32_t st = sb + s * STGB;
        int k0 = s << 5;
        if (MODE == 0) {
            cpa_tile(st,              A0, lda, k0, tid);
            cpa_tile(st + TILE_B,     A1, lda, k0, tid);
            cpa_tile(st + 2 * TILE_B, B0, ldb, k0, tid);
            cpa_tile(st + 3 * TILE_B, B1, ldb, k0, tid);
        } else {
            cpa_tile(st,          A0, lda, k0, tid);
            cpa_tile(st + TILE_B, B0, ldb, k0, tid);
        }
        asm volatile("cp.async.commit_group;");
    }

    for (int c = 0; c < nch; c++) {
        asm volatile("cp.async.wait_group 1;");
        __syncthreads();
        if (c + NSTG - 1 < nch) {
            uint32_t st = sb + ((c + NSTG - 1) % NSTG) * STGB;
            int k0 = (c + NSTG - 1) << 5;
            if (MODE == 0) {
                cpa_tile(st,              A0, lda, k0, tid);
                cpa_tile(st + TILE_B,     A1, lda, k0, tid);
                cpa_tile(st + 2 * TILE_B, B0, ldb, k0, tid);
                cpa_tile(st + 3 * TILE_B, B1, ldb, k0, tid);
            } else {
                cpa_tile(st,          A0, lda, k0, tid);
                cpa_tile(st + TILE_B, B0, ldb, k0, tid);
            }
        }
        asm volatile("cp.async.commit_group;");

        const uint32_t st = sb + (c % NSTG) * STGB;
#pragma unroll
        for (int k16 = 0; k16 < 2; k16++) {
            if (MODE == 1) {
                uint32_t fA[4][4], fB[4][4];
#pragma unroll
                for (int mt = 0; mt < 4; mt++)
                    ldmA(fA[mt], st, wm + mt * 16, k16, lane);
#pragma unroll
                for (int g = 0; g < 4; g++)
                    ldmB(fB[g], st + TILE_B, wn + g * 16, k16, lane);
#pragma unroll
                for (int mt = 0; mt < 4; mt++)
#pragma unroll
                    for (int nt = 0; nt < 8; nt++)
                        mmaH(acc[mt][nt], fA[mt], &fB[nt >> 1][(nt & 1) * 2]);
            } else {
                uint32_t fAh[4][4], fAl[4][4], fB[4][4];
#pragma unroll
                for (int mt = 0; mt < 4; mt++) {
                    ldmA(fAh[mt], st,          wm + mt * 16, k16, lane);
                    ldmA(fAl[mt], st + TILE_B, wm + mt * 16, k16, lane);
                }
                // B hi limb: HH + LH
#pragma unroll
                for (int g = 0; g < 4; g++)
                    ldmB(fB[g], st + 2 * TILE_B, wn + g * 16, k16, lane);
#pragma unroll
                for (int mt = 0; mt < 4; mt++)
#pragma unroll
                    for (int nt = 0; nt < 8; nt++)
                        mmaB(acc[mt][nt], fAh[mt], &fB[nt >> 1][(nt & 1) * 2]);
#pragma unroll
                for (int mt = 0; mt < 4; mt++)
#pragma unroll
                    for (int nt = 0; nt < 8; nt++)
                        mmaB(acc[mt][nt], fAl[mt], &fB[nt >> 1][(nt & 1) * 2]);
                // B lo limb: HL (overwrite fB)
#pragma unroll
                for (int g = 0; g < 4; g++)
                    ldmB(fB[g], st + 3 * TILE_B, wn + g * 16, k16, lane);
#pragma unroll
                for (int mt = 0; mt < 4; mt++)
#pragma unroll
                    for (int nt = 0; nt < 8; nt++)
                        mmaB(acc[mt][nt], fAh[mt], &fB[nt >> 1][(nt & 1) * 2]);
            }
        }
        __syncthreads();
    }

    // epilogue
    const int rr = lane >> 2;
    const int cc2 = (lane & 3) * 2;
#pragma unroll
    for (int mt = 0; mt < 4; mt++) {
#pragma unroll
        for (int nt = 0; nt < 8; nt++) {
            int row0 = bm + wm + mt * 16 + rr;
            int col = bn + wn + nt * 8 + cc2;
            float cb0 = cBias ? cBias[col] : 0.f;
            float cb1 = cBias ? cBias[col + 1] : 0.f;
#pragma unroll
            for (int h = 0; h < 2; h++) {
                int row = row0 + h * 8;
                float rb = rBias ? rBias[row] : 0.f;
                float v0 = acc[mt][nt][h * 2 + 0] + rb + cb0;
                float v1 = acc[mt][nt][h * 2 + 1] + rb + cb1;
                long o = (long)bz * oS + (long)row * ldc + col;
                if (OUT == 0) {
                    *(float2*)(outF + o) = make_float2(v0, v1);
                } else if (OUT == 1) {
                    st_split2(oH + o, oL + o, v0, v1);
                } else {
                    __half* hp = reinterpret_cast<__half*>(oH);
                    *(half2*)(hp + o) = __floats2half2_rn(v0, v1);
                }
            }
        }
    }
}

// ---------------- elementwise kernels ----------------
// seg0: gw -> fp16 single; seg1: tw -> bf16 pair; seg2: pw -> bf16 pair; seg3: ww -> fp16 single
__global__ void __launch_bounds__(256) split_w4(
    const float* __restrict__ w0, const float* __restrict__ w1,
    const float* __restrict__ w2, const float* __restrict__ w3,
    __half* __restrict__ gf,
    bf16* __restrict__ th, bf16* __restrict__ tl,
    bf16* __restrict__ ph, bf16* __restrict__ pl,
    __half* __restrict__ wf)
{
    const int seg = blockIdx.x >> 11;
    const int i = (blockIdx.x & 2047) * 256 + threadIdx.x;
    if (seg == 0) {
        gf[i] = __float2half_rn(w0[i]);
    } else if (seg == 3) {
        wf[i] = __float2half_rn(w3[i]);
    } else {
        const float* w = seg == 1 ? w1 : w2;
        bf16* hi = seg == 1 ? th : ph;
        bf16* lo = seg == 1 ? tl : pl;
        float v = w[i];
        bf16 h = __float2bfloat16(v);
        hi[i] = h;
        lo[i] = __float2bfloat16(v - __bfloat162float(h));
    }
}

// x (b,c,n) -> xT (b,n,c): bf16 hi/lo + single fp16
__global__ void __launch_bounds__(256) xpose_split(const float* __restrict__ x,
                                                   bf16* __restrict__ hi, bf16* __restrict__ lo,
                                                   __half* __restrict__ xf)
{
    __shared__ float t[32][33];
    const int b = blockIdx.z, n0 = blockIdx.x * 32, c0 = blockIdx.y * 32;
    const int tx = threadIdx.x & 31, ty = threadIdx.x >> 5;
#pragma unroll
    for (int i = 0; i < 4; i++) {
        int r = ty + i * 8;
        t[r][tx] = x[((long)b * CC + c0 + r) * NT + n0 + tx];
    }
    __syncthreads();
#pragma unroll
    for (int i = 0; i < 4; i++) {
        int r = ty + i * 8;
        float v = t[tx][r];
        long o = ((long)b * NT + n0 + r) * CC + c0 + tx;
        bf16 h = __float2bfloat16(v);
        hi[o] = h;
        lo[o] = __float2bfloat16(v - __bfloat162float(h));
        xf[o] = __float2half_rn(v);
    }
}

__global__ void __launch_bounds__(256) softmax_h(const float* __restrict__ f,
                                                 __half* __restrict__ at)
{
    const float4* pv = (const float4*)(f + (size_t)blockIdx.x * NT);
    const int tid = threadIdx.x;
    float4 a = pv[tid], b = pv[tid + 256];
    float m = fmaxf(fmaxf(fmaxf(a.x, a.y), fmaxf(a.z, a.w)),
                    fmaxf(fmaxf(b.x, b.y), fmaxf(b.z, b.w)));
    __shared__ float red[8];
#pragma unroll
    for (int o = 16; o > 0; o >>= 1) m = fmaxf(m, __shfl_xor_sync(~0u, m, o));
    if ((tid & 31) == 0) red[tid >> 5] = m;
    __syncthreads();
    float mm = red[0];
#pragma unroll
    for (int i = 1; i < 8; i++) mm = fmaxf(mm, red[i]);
    __syncthreads();
    a.x = expf(a.x - mm); a.y = expf(a.y - mm); a.z = expf(a.z - mm); a.w = expf(a.w - mm);
    b.x = expf(b.x - mm); b.y = expf(b.y - mm); b.z = expf(b.z - mm); b.w = expf(b.w - mm);
    float s = (a.x + a.y) + (a.z + a.w) + (b.x + b.y) + (b.z + b.w);
#pragma unroll
    for (int o = 16; o > 0; o >>= 1) s += __shfl_xor_sync(~0u, s, o);
    if ((tid & 31) == 0) red[tid >> 5] = s;
    __syncthreads();
    float sum = 0.f;
#pragma unroll
    for (int i = 0; i < 8; i++) sum += red[i];
    float inv = 1.0f / sum;
    size_t off = (size_t)blockIdx.x * NT;
    *(half2*)(at + off + tid * 4)     = __floats2half2_rn(a.x * inv, a.y * inv);
    *(half2*)(at + off + tid * 4 + 2) = __floats2half2_rn(a.z * inv, a.w * inv);
    *(half2*)(at + off + 1024 + tid * 4)     = __floats2half2_rn(b.x * inv, b.y * inv);
    *(half2*)(at + off + 1024 + tid * 4 + 2) = __floats2half2_rn(b.z * inv, b.w * inv);
}

__global__ void __launch_bounds__(256)
bn_residual(const float* __restrict__ wy, const float* __restrict__ x,
            const float* __restrict__ gamma, const float* __restrict__ beta,
            float* __restrict__ out)
{
    const int c = blockIdx.x, tid = threadIdx.x;
    float vals[32], s = 0.f, ss = 0.f;
#pragma unroll
    for (int b = 0; b < BB; b++) {
        const float* p = wy + ((size_t)b * CC + c) * NT;
#pragma unroll
        for (int j = 0; j < 8; j++) {
            float v = p[tid + j * 256];
            vals[b * 8 + j] = v; s += v; ss += v * v;
        }
    }
    __shared__ float r1[8], r2[8];
#pragma unroll
    for (int o = 16; o > 0; o >>= 1) {
        s += __shfl_xor_sync(~0u, s, o);
        ss += __shfl_xor_sync(~0u, ss, o);
    }
    if ((tid & 31) == 0) { r1[tid >> 5] = s; r2[tid >> 5] = ss; }
    __syncthreads();
    s = 0.f; ss = 0.f;
#pragma unroll
    for (int i = 0; i < 8; i++) { s += r1[i]; ss += r2[i]; }
    const float cnt = (float)(BB * NT);
    float mean = s / cnt;
    float var = ss / cnt - mean * mean;
    float scale = rsqrtf(var + 1e-5f) * gamma[c];
    float shift = beta[c] - mean * scale;
#pragma unroll
    for (int b = 0; b < BB; b++) {
        size_t off = ((size_t)b * CC + c) * NT;
#pragma unroll
        for (int j = 0; j < 8; j++) {
            int n = tid + j * 256;
            out[off + n] = vals[b * 8 + j] * scale + shift + x[off + n];
        }
    }
}

// ---------------------------------------------------------------------------
extern "C" void kernel_launch(void* const* d_in, const int* in_sizes, int n_in,
                              void* d_out, int out_size)
{
    const float* x   = (const float*)d_in[0];
    const float* gw  = (const float*)d_in[1];
    const float* gb  = (const float*)d_in[2];
    const float* tw  = (const float*)d_in[3];
    const float* tb  = (const float*)d_in[4];
    const float* pw  = (const float*)d_in[5];
    const float* pb  = (const float*)d_in[6];
    const float* ww  = (const float*)d_in[7];
    const float* wb  = (const float*)d_in[8];
    const float* bg  = (const float*)d_in[9];
    const float* bbt = (const float*)d_in[10];
    float* out = (float*)d_out;

    bf16 *xTh, *xTl, *wth, *wtl, *wph, *wpl, *thh, *thl, *phh, *phl;
    __half *xTf, *wgf, *wwf, *gs, *at, *yv;
    float *ff, *wy;
    cudaGetSymbolAddress((void**)&xTh, s_xT_h); cudaGetSymbolAddress((void**)&xTl, s_xT_l);
    cudaGetSymbolAddress((void**)&xTf, s_xT_f);
    cudaGetSymbolAddress((void**)&wth, s_wt_h); cudaGetSymbolAddress((void**)&wtl, s_wt_l);
    cudaGetSymbolAddress((void**)&wph, s_wp_h); cudaGetSymbolAddress((void**)&wpl, s_wp_l);
    cudaGetSymbolAddress((void**)&wgf, s_wgF);  cudaGetSymbolAddress((void**)&wwf, s_wwF);
    cudaGetSymbolAddress((void**)&thh, s_th_h); cudaGetSymbolAddress((void**)&thl, s_th_l);
    cudaGetSymbolAddress((void**)&phh, s_ph_h); cudaGetSymbolAddress((void**)&phl, s_ph_l);
    cudaGetSymbolAddress((void**)&gs,  s_gs);   cudaGetSymbolAddress((void**)&at,  s_at);
    cudaGetSymbolAddress((void**)&yv,  s_y);
    cudaGetSymbolAddress((void**)&ff,  s_f);    cudaGetSymbolAddress((void**)&wy,  s_wy);

    cudaFuncSetAttribute(gemm_tc<0, 0>, cudaFuncAttributeMaxDynamicSharedMemorySize, SMEM_BF);
    cudaFuncSetAttribute(gemm_tc<1, 0>, cudaFuncAttributeMaxDynamicSharedMemorySize, SMEM_BF);
    cudaFuncSetAttribute(gemm_tc<0, 1>, cudaFuncAttributeMaxDynamicSharedMemorySize, SMEM_H1);
    cudaFuncSetAttribute(gemm_tc<2, 1>, cudaFuncAttributeMaxDynamicSharedMemorySize, SMEM_H1);

    split_w4<<<4 * 2048, 256>>>(gw, tw, pw, ww, wgf, wth, wtl, wph, wpl, wwf);
    xpose_split<<<dim3(NT / 32, CC / 32, BB), 256>>>(x, xTh, xTl, xTf);

    const long sXT = (long)NT * CC, sPR = (long)NT * CIN;
    const long sGS = (long)CIN * NT, sAT = (long)NT * NT, sWY = (long)CC * NT;

    // theta + phi fused (bf16 3-prod): rows=NT cols=CIN K=CC, z in [0,8)
    gemm_tc<1, 0><<<dim3(CIN / 128, NT / 128, 2 * BB), 128, SMEM_BF>>>(
        xTh, xTl, sXT, CC, wth, wtl, 0, CC, nullptr, thh, thl, sPR, CIN, nullptr, tb, CC,
        wph, wpl, pb, phh, phl);
    // g (fp16 1-prod): rows=CIN (o), cols=NT (m), K=CC; out fp16 [o,m], rBias=g_b
    gemm_tc<2, 1><<<dim3(NT / 128, CIN / 128, BB), 128, SMEM_H1>>>(
        (const bf16*)wgf, nullptr, 0, CC, (const bf16*)xTf, nullptr, sXT, CC,
        nullptr, (bf16*)gs, nullptr, sGS, NT, gb, nullptr, CC,
        nullptr, nullptr, nullptr, nullptr, nullptr);
    // f (bf16 3-prod): rows=NT cols=NT K=CIN, out fp32
    gemm_tc<0, 0><<<dim3(NT / 128, NT / 128, BB), 128, SMEM_BF>>>(
        thh, thl, sPR, CIN, phh, phl, sPR, CIN, ff, nullptr, nullptr, sAT, NT, nullptr, nullptr, CIN,
        nullptr, nullptr, nullptr, nullptr, nullptr);
    // softmax -> single fp16 attn
    softmax_h<<<BB * NT, 256>>>(ff, at);
    // y (fp16 1-prod): rows=NT (n), cols=CIN (o), K=NT; A=attn, B=g; out fp16 [n,o]
    gemm_tc<2, 1><<<dim3(CIN / 128, NT / 128, BB), 128, SMEM_H1>>>(
        (const bf16*)at, nullptr, sAT, NT, (const bf16*)gs, nullptr, sGS, NT,
        nullptr, (bf16*)yv, nullptr, sPR, CIN, nullptr, nullptr, NT,
        nullptr, nullptr, nullptr, nullptr, nullptr);
    // w_y (fp16 1-prod): rows=CC (c), cols=NT (n), K=CIN; A=ww, B=y; out fp32 + wb
    gemm_tc<0, 1><<<dim3(NT / 128, CC / 128, BB), 128, SMEM_H1>>>(
        (const bf16*)wwf, nullptr, 0, CIN, (const bf16*)yv, nullptr, sPR, CIN,
        wy, nullptr, nullptr, sWY, NT, wb, nullptr, CIN,
        nullptr, nullptr, nullptr, nullptr, nullptr);
    // BN + residual
    bn_residual<<<CC, 256>>>(wy, x, bg, bbt, out);
}

// round 14
// speedup vs baseline: 1.5747x; 1.0004x over previous
#include <cuda_runtime.h>
#include <cuda_bf16.h>
#include <cuda_fp16.h>
#include <cstdint>

typedef __nv_bfloat16 bf16;

#define BB 4
#define CC 1024
#define CIN 512
#define NT 2048

// ---------------- static scratch ----------------
__device__ __align__(256) bf16 s_xT_h[BB * NT * CC];
__device__ __align__(256) bf16 s_xT_l[BB * NT * CC];
__device__ __align__(256) bf16 s_wt_h[CIN * CC], s_wt_l[CIN * CC];
__device__ __align__(256) bf16 s_wp_h[CIN * CC], s_wp_l[CIN * CC];
__device__ __align__(256) bf16 s_th_h[BB * NT * CIN], s_th_l[BB * NT * CIN];
__device__ __align__(256) bf16 s_ph_h[BB * NT * CIN], s_ph_l[BB * NT * CIN];
__device__ __align__(256) float s_f[BB * NT * NT];
__device__ __align__(256) __half s_xT_f[BB * NT * CC];
__device__ __align__(256) __half s_wgF[CIN * CC];
__device__ __align__(256) __half s_wwF[CC * CIN];
__device__ __align__(256) __half s_gs[BB * CIN * NT];
__device__ __align__(256) __half s_at[BB * NT * NT];
__device__ __align__(256) __half s_y[BB * NT * CIN];
__device__ __align__(256) float s_wy[BB * CC * NT];

// ---------------- helpers ----------------
__device__ __forceinline__ uint32_t smem_u32(const void* p) {
    uint32_t a;
    asm("{ .reg .u64 t; cvta.to.shared.u64 t, %1; cvt.u32.u64 %0, t; }" : "=r"(a) : "l"(p));
    return a;
}
__device__ __forceinline__ void st_split2(bf16* hi, bf16* lo, float v0, float v1) {
    bf16 h0 = __float2bfloat16(v0), h1 = __float2bfloat16(v1);
    *(uint32_t*)hi = (uint32_t)__bfloat16_as_ushort(h0) |
                     ((uint32_t)__bfloat16_as_ushort(h1) << 16);
    bf16 l0 = __float2bfloat16(v0 - __bfloat162float(h0));
    bf16 l1 = __float2bfloat16(v1 - __bfloat162float(h1));
    *(uint32_t*)lo = (uint32_t)__bfloat16_as_ushort(l0) |
                     ((uint32_t)__bfloat16_as_ushort(l1) << 16);
}
__device__ __forceinline__ uint32_t pack_bf(float v0, float v1) {
    return (uint32_t)__bfloat16_as_ushort(__float2bfloat16(v0)) |
           ((uint32_t)__bfloat16_as_ushort(__float2bfloat16(v1)) << 16);
}
__device__ __forceinline__ uint32_t h2_u32(half2 h) {
    uint32_t u;
    *(half2*)&u = h;
    return u;
}

// ---------------- HMMA GEMM ----------------
// MODE 0: bf16, A/B 2-limb, 3 products (HH+LH+HL), K-chunk 32
// MODE 1: fp16, single-limb, 1 product, K-chunk 64
// CTA 128x128, 4 warps (2x2) of 64x64, 3-stage cp.async, 2 CTA/SM (96 KB smem).
#define NSTG 3
#define SMEM_BF (NSTG * 4 * 8192)    // 96 KB
#define SMEM_H1 (NSTG * 2 * 16384)   // 96 KB

// swizzled 16B-vector offset; W = row bytes (64 for K32 bf16-limb tiles, 128 for K64 fp16)
template <int W>
__device__ __forceinline__ uint32_t sw(int row, int kv) {
    if (W == 64) return (uint32_t)(row * 64 + ((kv ^ ((row >> 1) & 3)) << 4));
    else         return (uint32_t)(row * 128 + ((kv ^ (row & 7)) << 4));
}
template <int W>
__device__ __forceinline__ void cpa_tile(uint32_t sdst, const bf16* __restrict__ g,
                                         int ld, int k0, int tid) {
    constexpr int KV = W / 16;   // vectors per row
#pragma unroll
    for (int i = 0; i < KV; i++) {
        int idx = tid + i * 128;
        int row = idx / KV;
        int kv  = idx % KV;
        uint32_t dst = sdst + sw<W>(row, kv);
        const void* src = g + (long)row * ld + k0 + kv * 8;
        asm volatile("cp.async.cg.shared.global [%0], [%1], 16;" :: "r"(dst), "l"(src));
    }
}
template <int W>
__device__ __forceinline__ void ldmA(uint32_t* r, uint32_t base, int m0, int k16, int lane) {
    int m = m0 + (lane & 15);
    int kv = k16 * 2 + (lane >> 4);
    uint32_t addr = base + sw<W>(m, kv);
    asm volatile("ldmatrix.sync.aligned.m8n8.x4.shared.b16 {%0,%1,%2,%3}, [%4];"
                 : "=r"(r[0]), "=r"(r[1]), "=r"(r[2]), "=r"(r[3]) : "r"(addr));
}
template <int W>
__device__ __forceinline__ void ldmB(uint32_t* r, uint32_t base, int n0, int k16, int lane) {
    int row = n0 + (lane & 7) + ((lane >> 4) << 3);
    int kv = k16 * 2 + ((lane >> 3) & 1);
    uint32_t addr = base + sw<W>(row, kv);
    asm volatile("ldmatrix.sync.aligned.m8n8.x4.shared.b16 {%0,%1,%2,%3}, [%4];"
                 : "=r"(r[0]), "=r"(r[1]), "=r"(r[2]), "=r"(r[3]) : "r"(addr));
}
__device__ __forceinline__ void mmaB(float* c, const uint32_t* a, const uint32_t* b) {
    asm volatile(
        "mma.sync.aligned.m16n8k16.row.col.f32.bf16.bf16.f32 "
        "{%0,%1,%2,%3},{%4,%5,%6,%7},{%8,%9},{%0,%1,%2,%3};"
        : "+f"(c[0]), "+f"(c[1]), "+f"(c[2]), "+f"(c[3])
        : "r"(a[0]), "r"(a[1]), "r"(a[2]), "r"(a[3]), "r"(b[0]), "r"(b[1]));
}
__device__ __forceinline__ void mmaH(float* c, const uint32_t* a, const uint32_t* b) {
    asm volatile(
        "mma.sync.aligned.m16n8k16.row.col.f32.f16.f16.f32 "
        "{%0,%1,%2,%3},{%4,%5,%6,%7},{%8,%9},{%0,%1,%2,%3};"
        : "+f"(c[0]), "+f"(c[1]), "+f"(c[2]), "+f"(c[3])
        : "r"(a[0]), "r"(a[1]), "r"(a[2]), "r"(a[3]), "r"(b[0]), "r"(b[1]));
}

// OUT: 0 = fp32 (+rBias,+cBias), 1 = split bf16 (+biases), 2 = single fp16 (+rBias)
template <int OUT, int MODE>
__global__ void __launch_bounds__(128, 2)
gemm_tc(const bf16* __restrict__ aH, const bf16* __restrict__ aL, long aS, int lda,
        const bf16* __restrict__ bH, const bf16* __restrict__ bL, long bS, int ldb,
        float* __restrict__ outF, bf16* __restrict__ oH, bf16* __restrict__ oL,
        long oS, int ldc, const float* __restrict__ rBias,
        const float* __restrict__ cBias, int K,
        const bf16* __restrict__ bH2, const bf16* __restrict__ bL2,
        const float* __restrict__ cBias2,
        bf16* __restrict__ oH2, bf16* __restrict__ oL2)
{
    constexpr int KCH = (MODE == 0) ? 32 : 64;     // K per chunk
    constexpr int W   = KCH * 2;                   // row bytes
    constexpr int TB  = 128 * W;                   // tile bytes
    constexpr int NTL = (MODE == 0) ? 4 : 2;
    constexpr int STGB = NTL * TB;
    constexpr int NK16 = KCH / 16;
    extern __shared__ char smraw[];
    const uint32_t sb = smem_u32(smraw);

    const int tid = threadIdx.x, wid = tid >> 5, lane = tid & 31;
    const int bn = blockIdx.x * 128, bm = blockIdx.y * 128;
    int bz = blockIdx.z;
    if (bH2 && bz >= BB) {
        bz -= BB;
        bH = bH2; bL = bL2; cBias = cBias2; oH = oH2; oL = oL2;
    }
    const int wm = (wid & 1) * 64;
    const int wn = (wid >> 1) * 64;

    const bf16* A0 = aH + (long)bz * aS + (long)bm * lda;
    const bf16* A1 = (MODE == 0) ? aL + (long)bz * aS + (long)bm * lda : nullptr;
    const bf16* B0 = bH + (long)bz * bS + (long)bn * ldb;
    const bf16* B1 = (MODE == 0) ? bL + (long)bz * bS + (long)bn * ldb : nullptr;
    const int nch = K / KCH;

    float acc[4][8][4];
#pragma unroll
    for (int i = 0; i < 4; i++)
#pragma unroll
        for (int j = 0; j < 8; j++)
#pragma unroll
            for (int e = 0; e < 4; e++) acc[i][j][e] = 0.f;

#pragma unroll
    for (int s = 0; s < NSTG - 1; s++) {
        uint32_t st = sb + s * STGB;
        int k0 = s * KCH;
        if (MODE == 0) {
            cpa_tile<W>(st,          A0, lda, k0, tid);
            cpa_tile<W>(st + TB,     A1, lda, k0, tid);
            cpa_tile<W>(st + 2 * TB, B0, ldb, k0, tid);
            cpa_tile<W>(st + 3 * TB, B1, ldb, k0, tid);
        } else {
            cpa_tile<W>(st,      A0, lda, k0, tid);
            cpa_tile<W>(st + TB, B0, ldb, k0, tid);
        }
        asm volatile("cp.async.commit_group;");
    }

    for (int c = 0; c < nch; c++) {
        asm volatile("cp.async.wait_group 1;");
        __syncthreads();
        if (c + NSTG - 1 < nch) {
            uint32_t st = sb + ((c + NSTG - 1) % NSTG) * STGB;
            int k0 = (c + NSTG - 1) * KCH;
            if (MODE == 0) {
                cpa_tile<W>(st,          A0, lda, k0, tid);
                cpa_tile<W>(st + TB,     A1, lda, k0, tid);
                cpa_tile<W>(st + 2 * TB, B0, ldb, k0, tid);
                cpa_tile<W>(st + 3 * TB, B1, ldb, k0, tid);
            } else {
                cpa_tile<W>(st,      A0, lda, k0, tid);
                cpa_tile<W>(st + TB, B0, ldb, k0, tid);
            }
        }
        asm volatile("cp.async.commit_group;");

        const uint32_t st = sb + (c % NSTG) * STGB;
#pragma unroll
        for (int k16 = 0; k16 < NK16; k16++) {
            if (MODE == 1) {
                uint32_t fA[4][4], fB[4][4];
#pragma unroll
                for (int mt = 0; mt < 4; mt++)
                    ldmA<W>(fA[mt], st, wm + mt * 16, k16, lane);
#pragma unroll
                for (int g = 0; g < 4; g++)
                    ldmB<W>(fB[g], st + TB, wn + g * 16, k16, lane);
#pragma unroll
                for (int mt = 0; mt < 4; mt++)
#pragma unroll
                    for (int nt = 0; nt < 8; nt++)
                        mmaH(acc[mt][nt], fA[mt], &fB[nt >> 1][(nt & 1) * 2]);
            } else {
                uint32_t fAh[4][4], fAl[4][4], fB[4][4];
#pragma unroll
                for (int mt = 0; mt < 4; mt++) {
                    ldmA<W>(fAh[mt], st,      wm + mt * 16, k16, lane);
                    ldmA<W>(fAl[mt], st + TB, wm + mt * 16, k16, lane);
                }
#pragma unroll
                for (int g = 0; g < 4; g++)
                    ldmB<W>(fB[g], st + 2 * TB, wn + g * 16, k16, lane);
#pragma unroll
                for (int mt = 0; mt < 4; mt++)
#pragma unroll
                    for (int nt = 0; nt < 8; nt++)
                        mmaB(acc[mt][nt], fAh[mt], &fB[nt >> 1][(nt & 1) * 2]);
#pragma unroll
                for (int mt = 0; mt < 4; mt++)
#pragma unroll
                    for (int nt = 0; nt < 8; nt++)
                        mmaB(acc[mt][nt], fAl[mt], &fB[nt >> 1][(nt & 1) * 2]);
#pragma unroll
                for (int g = 0; g < 4; g++)
                    ldmB<W>(fB[g], st + 3 * TB, wn + g * 16, k16, lane);
#pragma unroll
                for (int mt = 0; mt < 4; mt++)
#pragma unroll
                    for (int nt = 0; nt < 8; nt++)
                        mmaB(acc[mt][nt], fAh[mt], &fB[nt >> 1][(nt & 1) * 2]);
            }
        }
        __syncthreads();
    }

    // epilogue
    const int rr = lane >> 2;
    const int cc2 = (lane & 3) * 2;
#pragma unroll
    for (int mt = 0; mt < 4; mt++) {
#pragma unroll
        for (int nt = 0; nt < 8; nt++) {
            int row0 = bm + wm + mt * 16 + rr;
            int col = bn + wn + nt * 8 + cc2;
            float cb0 = cBias ? cBias[col] : 0.f;
            float cb1 = cBias ? cBias[col + 1] : 0.f;
#pragma unroll
            for (int h = 0; h < 2; h++) {
                int row = row0 + h * 8;
                float rb = rBias ? rBias[row] : 0.f;
                float v0 = acc[mt][nt][h * 2 + 0] + rb + cb0;
                float v1 = acc[mt][nt][h * 2 + 1] + rb + cb1;
                long o = (long)bz * oS + (long)row * ldc + col;
                if (OUT == 0) {
                    *(float2*)(outF + o) = make_float2(v0, v1);
                } else if (OUT == 1) {
                    st_split2(oH + o, oL + o, v0, v1);
                } else {
                    __half* hp = reinterpret_cast<__half*>(oH);
                    *(half2*)(hp + o) = __floats2half2_rn(v0, v1);
                }
            }
        }
    }
}

// ---------------- elementwise kernels ----------------
// 2 elems/thread, packed 4B stores. seg0: gw->fp16; seg1: tw->bf16 pair; seg2: pw->bf16 pair; seg3: ww->fp16
__global__ void __launch_bounds__(256) split_w4(
    const float* __restrict__ w0, const float* __restrict__ w1,
    const float* __restrict__ w2, const float* __restrict__ w3,
    __half* __restrict__ gf,
    bf16* __restrict__ th, bf16* __restrict__ tl,
    bf16* __restrict__ ph, bf16* __restrict__ pl,
    __half* __restrict__ wf)
{
    const int seg = blockIdx.x >> 10;               // 1024 blocks/segment
    const int i = ((blockIdx.x & 1023) * 256 + threadIdx.x) * 2;
    if (seg == 0) {
        float2 v = *(const float2*)(w0 + i);
        *(half2*)(gf + i) = __floats2half2_rn(v.x, v.y);
    } else if (seg == 3) {
        float2 v = *(const float2*)(w3 + i);
        *(half2*)(wf + i) = __floats2half2_rn(v.x, v.y);
    } else {
        const float* w = seg == 1 ? w1 : w2;
        bf16* hi = seg == 1 ? th : ph;
        bf16* lo = seg == 1 ? tl : pl;
        float2 v = *(const float2*)(w + i);
        st_split2(hi + i, lo + i, v.x, v.y);
    }
}

// x (b,c,n) -> xT (b,n,c): 32n x 64c tiles, packed 4B stores
__global__ void __launch_bounds__(256) xpose_split(const float* __restrict__ x,
                                                   bf16* __restrict__ hi, bf16* __restrict__ lo,
                                                   __half* __restrict__ xf)
{
    __shared__ float t[64][33];
    const int b = blockIdx.z, n0 = blockIdx.x * 32, c0 = blockIdx.y * 64;
    const int tx = threadIdx.x & 31, ty = threadIdx.x >> 5;
#pragma unroll
    for (int i = 0; i < 8; i++) {
        int r = ty + i * 8;          // c-row 0..63
        t[r][tx] = x[((long)b * CC + c0 + r) * NT + n0 + tx];
    }
    __syncthreads();
#pragma unroll
    for (int i = 0; i < 4; i++) {
        int n = ty + i * 8;          // 0..31
        float v0 = t[tx * 2][n];
        float v1 = t[tx * 2 + 1][n];
        long o = ((long)b * NT + n0 + n) * CC + c0 + tx * 2;
        *(uint32_t*)(hi + o) = pack_bf(v0, v1);
        bf16 h0 = __float2bfloat16(v0), h1 = __float2bfloat16(v1);
        *(uint32_t*)(lo + o) = pack_bf(v0 - __bfloat162float(h0), v1 - __bfloat162float(h1));
        *(half2*)(xf + o) = __floats2half2_rn(v0, v1);
    }
}

__global__ void __launch_bounds__(256) softmax_h(const float* __restrict__ f,
                                                 __half* __restrict__ at)
{
    const float4* pv = (const float4*)(f + (size_t)blockIdx.x * NT);
    const int tid = threadIdx.x;
    float4 a = pv[tid], b = pv[tid + 256];
    float m = fmaxf(fmaxf(fmaxf(a.x, a.y), fmaxf(a.z, a.w)),
                    fmaxf(fmaxf(b.x, b.y), fmaxf(b.z, b.w)));
    __shared__ float red[8];
#pragma unroll
    for (int o = 16; o > 0; o >>= 1) m = fmaxf(m, __shfl_xor_sync(~0u, m, o));
    if ((tid & 31) == 0) red[tid >> 5] = m;
    __syncthreads();
    float mm = red[0];
#pragma unroll
    for (int i = 1; i < 8; i++) mm = fmaxf(mm, red[i]);
    __syncthreads();
    a.x = expf(a.x - mm); a.y = expf(a.y - mm); a.z = expf(a.z - mm); a.w = expf(a.w - mm);
    b.x = expf(b.x - mm); b.y = expf(b.y - mm); b.z = expf(b.z - mm); b.w = expf(b.w - mm);
    float s = (a.x + a.y) + (a.z + a.w) + (b.x + b.y) + (b.z + b.w);
#pragma unroll
    for (int o = 16; o > 0; o >>= 1) s += __shfl_xor_sync(~0u, s, o);
    if ((tid & 31) == 0) red[tid >> 5] = s;
    __syncthreads();
    float sum = 0.f;
#pragma unroll
    for (int i = 0; i < 8; i++) sum += red[i];
    float inv = 1.0f / sum;
    size_t off = (size_t)blockIdx.x * NT;
    uint2 pa = make_uint2(h2_u32(__floats2half2_rn(a.x * inv, a.y * inv)),
                          h2_u32(__floats2half2_rn(a.z * inv, a.w * inv)));
    *(uint2*)(at + off + tid * 4) = pa;
    uint2 pb = make_uint2(h2_u32(__floats2half2_rn(b.x * inv, b.y * inv)),
                          h2_u32(__floats2half2_rn(b.z * inv, b.w * inv)));
    *(uint2*)(at + off + 1024 + tid * 4) = pb;
}

__global__ void __launch_bounds__(256)
bn_residual(const float* __restrict__ wy, const float* __restrict__ x,
            const float* __restrict__ gamma, const float* __restrict__ beta,
            float* __restrict__ out)
{
    const int c = blockIdx.x, tid = threadIdx.x;
    float vals[32], s = 0.f, ss = 0.f;
#pragma unroll
    for (int b = 0; b < BB; b++) {
        const float* p = wy + ((size_t)b * CC + c) * NT;
#pragma unroll
        for (int j = 0; j < 8; j++) {
            float v = p[tid + j * 256];
            vals[b * 8 + j] = v; s += v; ss += v * v;
        }
    }
    __shared__ float r1[8], r2[8];
#pragma unroll
    for (int o = 16; o > 0; o >>= 1) {
        s += __shfl_xor_sync(~0u, s, o);
        ss += __shfl_xor_sync(~0u, ss, o);
    }
    if ((tid & 31) == 0) { r1[tid >> 5] = s; r2[tid >> 5] = ss; }
    __syncthreads();
    s = 0.f; ss = 0.f;
#pragma unroll
    for (int i = 0; i < 8; i++) { s += r1[i]; ss += r2[i]; }
    const float cnt = (float)(BB * NT);
    float mean = s / cnt;
    float var = ss / cnt - mean * mean;
    float scale = rsqrtf(var + 1e-5f) * gamma[c];
    float shift = beta[c] - mean * scale;
#pragma unroll
    for (int b = 0; b < BB; b++) {
        size_t off = ((size_t)b * CC + c) * NT;
#pragma unroll
        for (int j = 0; j < 8; j++) {
            int n = tid + j * 256;
            out[off + n] = vals[b * 8 + j] * scale + shift + x[off + n];
        }
    }
}

// ---------------------------------------------------------------------------
extern "C" void kernel_launch(void* const* d_in, const int* in_sizes, int n_in,
                              void* d_out, int out_size)
{
    const float* x   = (const float*)d_in[0];
    const float* gw  = (const float*)d_in[1];
    const float* gb  = (const float*)d_in[2];
    const float* tw  = (const float*)d_in[3];
    const float* tb  = (const float*)d_in[4];
    const float* pw  = (const float*)d_in[5];
    const float* pb  = (const float*)d_in[6];
    const float* ww  = (const float*)d_in[7];
    const float* wb  = (const float*)d_in[8];
    const float* bg  = (const float*)d_in[9];
    const float* bbt = (const float*)d_in[10];
    float* out = (float*)d_out;

    bf16 *xTh, *xTl, *wth, *wtl, *wph, *wpl, *thh, *thl, *phh, *phl;
    __half *xTf, *wgf, *wwf, *gs, *at, *yv;
    float *ff, *wy;
    cudaGetSymbolAddress((void**)&xTh, s_xT_h); cudaGetSymbolAddress((void**)&xTl, s_xT_l);
    cudaGetSymbolAddress((void**)&xTf, s_xT_f);
    cudaGetSymbolAddress((void**)&wth, s_wt_h); cudaGetSymbolAddress((void**)&wtl, s_wt_l);
    cudaGetSymbolAddress((void**)&wph, s_wp_h); cudaGetSymbolAddress((void**)&wpl, s_wp_l);
    cudaGetSymbolAddress((void**)&wgf, s_wgF);  cudaGetSymbolAddress((void**)&wwf, s_wwF);
    cudaGetSymbolAddress((void**)&thh, s_th_h); cudaGetSymbolAddress((void**)&thl, s_th_l);
    cudaGetSymbolAddress((void**)&phh, s_ph_h); cudaGetSymbolAddress((void**)&phl, s_ph_l);
    cudaGetSymbolAddress((void**)&gs,  s_gs);   cudaGetSymbolAddress((void**)&at,  s_at);
    cudaGetSymbolAddress((void**)&yv,  s_y);
    cudaGetSymbolAddress((void**)&ff,  s_f);    cudaGetSymbolAddress((void**)&wy,  s_wy);

    cudaFuncSetAttribute(gemm_tc<0, 0>, cudaFuncAttributeMaxDynamicSharedMemorySize, SMEM_BF);
    cudaFuncSetAttribute(gemm_tc<1, 0>, cudaFuncAttributeMaxDynamicSharedMemorySize, SMEM_BF);
    cudaFuncSetAttribute(gemm_tc<0, 1>, cudaFuncAttributeMaxDynamicSharedMemorySize, SMEM_H1);
    cudaFuncSetAttribute(gemm_tc<2, 1>, cudaFuncAttributeMaxDynamicSharedMemorySize, SMEM_H1);

    split_w4<<<4 * 1024, 256>>>(gw, tw, pw, ww, wgf, wth, wtl, wph, wpl, wwf);
    xpose_split<<<dim3(NT / 32, CC / 64, BB), 256>>>(x, xTh, xTl, xTf);

    const long sXT = (long)NT * CC, sPR = (long)NT * CIN;
    const long sGS = (long)CIN * NT, sAT = (long)NT * NT, sWY = (long)CC * NT;

    // theta + phi fused (bf16 3-prod): rows=NT cols=CIN K=CC, z in [0,8)
    gemm_tc<1, 0><<<dim3(CIN / 128, NT / 128, 2 * BB), 128, SMEM_BF>>>(
        xTh, xTl, sXT, CC, wth, wtl, 0, CC, nullptr, thh, thl, sPR, CIN, nullptr, tb, CC,
        wph, wpl, pb, phh, phl);
    // g (fp16 1-prod): rows=CIN (o), cols=NT (m), K=CC; out fp16 [o,m] + g_b
    gemm_tc<2, 1><<<dim3(NT / 128, CIN / 128, BB), 128, SMEM_H1>>>(
        (const bf16*)wgf, nullptr, 0, CC, (const bf16*)xTf, nullptr, sXT, CC,
        nullptr, (bf16*)gs, nullptr, sGS, NT, gb, nullptr, CC,
        nullptr, nullptr, nullptr, nullptr, nullptr);
    // f (bf16 3-prod): rows=NT cols=NT K=CIN, out fp32
    gemm_tc<0, 0><<<dim3(NT / 128, NT / 128, BB), 128, SMEM_BF>>>(
        thh, thl, sPR, CIN, phh, phl, sPR, CIN, ff, nullptr, nullptr, sAT, NT, nullptr, nullptr, CIN,
        nullptr, nullptr, nullptr, nullptr, nullptr);
    // softmax -> single fp16 attn
    softmax_h<<<BB * NT, 256>>>(ff, at);
    // y (fp16 1-prod): rows=NT (n), cols=CIN (o), K=NT; out fp16 [n,o]
    gemm_tc<2, 1><<<dim3(CIN / 128, NT / 128, BB), 128, SMEM_H1>>>(
        (const bf16*)at, nullptr, sAT, NT, (const bf16*)gs, nullptr, sGS, NT,
        nullptr, (bf16*)yv, nullptr, sPR, CIN, nullptr, nullptr, NT,
        nullptr, nullptr, nullptr, nullptr, nullptr);
    // w_y (fp16 1-prod): rows=CC (c), cols=NT (n), K=CIN; out fp32 + wb
    gemm_tc<0, 1><<<dim3(NT / 128, CC / 128, BB), 128, SMEM_H1>>>(
        (const bf16*)wwf, nullptr, 0, CIN, (const bf16*)yv, nullptr, sPR, CIN,
        wy, nullptr, nullptr, sWY, NT, wb, nullptr, CIN,
        nullptr, nullptr, nullptr, nullptr, nullptr);
    // BN + residual
    bn_residual<<<CC, 256>>>(wy, x, bg, bbt, out);
}

// round 15
// speedup vs baseline: 1.6058x; 1.0197x over previous
#include <cuda_runtime.h>
#include <cuda_bf16.h>
#include <cuda_fp16.h>
#include <cstdint>

typedef __nv_bfloat16 bf16;

#define BB 4
#define CC 1024
#define CIN 512
#define NT 2048

// ---------------- static scratch ----------------
__device__ __align__(256) bf16 s_xT_h[BB * NT * CC];
__device__ __align__(256) bf16 s_xT_l[BB * NT * CC];
__device__ __align__(256) bf16 s_wt_h[CIN * CC], s_wt_l[CIN * CC];
__device__ __align__(256) bf16 s_wp_h[CIN * CC], s_wp_l[CIN * CC];
__device__ __align__(256) bf16 s_th_h[BB * NT * CIN], s_th_l[BB * NT * CIN];
__device__ __align__(256) bf16 s_ph_h[BB * NT * CIN], s_ph_l[BB * NT * CIN];
__device__ __align__(256) float s_f[BB * NT * NT];
__device__ __align__(256) __half s_xT_f[BB * NT * CC];
__device__ __align__(256) __half s_wgF[CIN * CC];
__device__ __align__(256) __half s_wwF[CC * CIN];
__device__ __align__(256) __half s_gs[BB * CIN * NT];
__device__ __align__(256) __half s_at[BB * NT * NT];
__device__ __align__(256) __half s_y[BB * NT * CIN];
__device__ __align__(256) __half s_wyh[BB * CC * NT];

// ---------------- helpers ----------------
__device__ __forceinline__ uint32_t smem_u32(const void* p) {
    uint32_t a;
    asm("{ .reg .u64 t; cvta.to.shared.u64 t, %1; cvt.u32.u64 %0, t; }" : "=r"(a) : "l"(p));
    return a;
}
__device__ __forceinline__ void st_split2(bf16* hi, bf16* lo, float v0, float v1) {
    bf16 h0 = __float2bfloat16(v0), h1 = __float2bfloat16(v1);
    *(uint32_t*)hi = (uint32_t)__bfloat16_as_ushort(h0) |
                     ((uint32_t)__bfloat16_as_ushort(h1) << 16);
    bf16 l0 = __float2bfloat16(v0 - __bfloat162float(h0));
    bf16 l1 = __float2bfloat16(v1 - __bfloat162float(h1));
    *(uint32_t*)lo = (uint32_t)__bfloat16_as_ushort(l0) |
                     ((uint32_t)__bfloat16_as_ushort(l1) << 16);
}
__device__ __forceinline__ uint32_t pack_bf(float v0, float v1) {
    return (uint32_t)__bfloat16_as_ushort(__float2bfloat16(v0)) |
           ((uint32_t)__bfloat16_as_ushort(__float2bfloat16(v1)) << 16);
}
__device__ __forceinline__ uint32_t h2_u32(half2 h) {
    uint32_t u;
    *(half2*)&u = h;
    return u;
}

// ---------------- HMMA GEMM ----------------
// MODE 0: bf16, A/B 2-limb, 3 products (HH+LH+HL)
// MODE 1: fp16, single-limb, 1 product
// CTA 128x128, 4 warps (2x2) of 64x64, K-chunk 32, 3-stage cp.async, 2 CTA/SM.
#define NSTG 3
#define TILE_B 8192
#define SMEM_BF (NSTG * 4 * TILE_B)   // 96 KB
#define SMEM_H1 (NSTG * 2 * TILE_B)   // 48 KB

__device__ __forceinline__ uint32_t sw(int row, int kv) {
    return (uint32_t)(row * 64 + ((kv ^ ((row >> 1) & 3)) << 4));
}
__device__ __forceinline__ void cpa_tile(uint32_t sdst, const bf16* __restrict__ g,
                                         int ld, int k0, int tid) {
#pragma unroll
    for (int i = 0; i < 4; i++) {
        int idx = tid + i * 128;       // 0..511
        int row = idx >> 2;            // 0..127
        int kv  = idx & 3;
        uint32_t dst = sdst + sw(row, kv);
        const void* src = g + (long)row * ld + k0 + kv * 8;
        asm volatile("cp.async.cg.shared.global [%0], [%1], 16;" :: "r"(dst), "l"(src));
    }
}
__device__ __forceinline__ void ldmA(uint32_t* r, uint32_t base, int m0, int k16, int lane) {
    int m = m0 + (lane & 15);
    int kv = k16 * 2 + (lane >> 4);
    uint32_t addr = base + sw(m, kv);
    asm volatile("ldmatrix.sync.aligned.m8n8.x4.shared.b16 {%0,%1,%2,%3}, [%4];"
                 : "=r"(r[0]), "=r"(r[1]), "=r"(r[2]), "=r"(r[3]) : "r"(addr));
}
__device__ __forceinline__ void ldmB(uint32_t* r, uint32_t base, int n0, int k16, int lane) {
    int row = n0 + (lane & 7) + ((lane >> 4) << 3);
    int kv = k16 * 2 + ((lane >> 3) & 1);
    uint32_t addr = base + sw(row, kv);
    asm volatile("ldmatrix.sync.aligned.m8n8.x4.shared.b16 {%0,%1,%2,%3}, [%4];"
                 : "=r"(r[0]), "=r"(r[1]), "=r"(r[2]), "=r"(r[3]) : "r"(addr));
}
__device__ __forceinline__ void mmaB(float* c, const uint32_t* a, const uint32_t* b) {
    asm volatile(
        "mma.sync.aligned.m16n8k16.row.col.f32.bf16.bf16.f32 "
        "{%0,%1,%2,%3},{%4,%5,%6,%7},{%8,%9},{%0,%1,%2,%3};"
        : "+f"(c[0]), "+f"(c[1]), "+f"(c[2]), "+f"(c[3])
        : "r"(a[0]), "r"(a[1]), "r"(a[2]), "r"(a[3]), "r"(b[0]), "r"(b[1]));
}
__device__ __forceinline__ void mmaH(float* c, const uint32_t* a, const uint32_t* b) {
    asm volatile(
        "mma.sync.aligned.m16n8k16.row.col.f32.f16.f16.f32 "
        "{%0,%1,%2,%3},{%4,%5,%6,%7},{%8,%9},{%0,%1,%2,%3};"
        : "+f"(c[0]), "+f"(c[1]), "+f"(c[2]), "+f"(c[3])
        : "r"(a[0]), "r"(a[1]), "r"(a[2]), "r"(a[3]), "r"(b[0]), "r"(b[1]));
}

// OUT: 0 = fp32 (+rBias,+cBias), 1 = split bf16 (+biases), 2 = single fp16 (+rBias)
template <int OUT, int MODE>
__global__ void __launch_bounds__(128, 2)
gemm_tc(const bf16* __restrict__ aH, const bf16* __restrict__ aL, long aS, int lda,
        const bf16* __restrict__ bH, const bf16* __restrict__ bL, long bS, int ldb,
        float* __restrict__ outF, bf16* __restrict__ oH, bf16* __restrict__ oL,
        long oS, int ldc, const float* __restrict__ rBias,
        const float* __restrict__ cBias, int K,
        const bf16* __restrict__ bH2, const bf16* __restrict__ bL2,
        const float* __restrict__ cBias2,
        bf16* __restrict__ oH2, bf16* __restrict__ oL2)
{
    constexpr int NTL = (MODE == 0) ? 4 : 2;
    constexpr int STGB = NTL * TILE_B;
    extern __shared__ char smraw[];
    const uint32_t sb = smem_u32(smraw);

    const int tid = threadIdx.x, wid = tid >> 5, lane = tid & 31;
    const int bn = blockIdx.x * 128, bm = blockIdx.y * 128;
    int bz = blockIdx.z;
    if (bH2 && bz >= BB) {
        bz -= BB;
        bH = bH2; bL = bL2; cBias = cBias2; oH = oH2; oL = oL2;
    }
    const int wm = (wid & 1) * 64;
    const int wn = (wid >> 1) * 64;

    const bf16* A0 = aH + (long)bz * aS + (long)bm * lda;
    const bf16* A1 = (MODE == 0) ? aL + (long)bz * aS + (long)bm * lda : nullptr;
    const bf16* B0 = bH + (long)bz * bS + (long)bn * ldb;
    const bf16* B1 = (MODE == 0) ? bL + (long)bz * bS + (long)bn * ldb : nullptr;
    const int nch = K >> 5;

    float acc[4][8][4];
#pragma unroll
    for (int i = 0; i < 4; i++)
#pragma unroll
        for (int j = 0; j < 8; j++)
#pragma unroll
            for (int e = 0; e < 4; e++) acc[i][j][e] = 0.f;

#pragma unroll
    for (int s = 0; s < NSTG - 1; s++) {
        uint32_t st = sb + s * STGB;
        int k0 = s << 5;
        if (MODE == 0) {
            cpa_tile(st,              A0, lda, k0, tid);
            cpa_tile(st + TILE_B,     A1, lda, k0, tid);
            cpa_tile(st + 2 * TILE_B, B0, ldb, k0, tid);
            cpa_tile(st + 3 * TILE_B, B1, ldb, k0, tid);
        } else {
            cpa_tile(st,          A0, lda, k0, tid);
            cpa_tile(st + TILE_B, B0, ldb, k0, tid);
        }
        asm volatile("cp.async.commit_group;");
    }

    for (int c = 0; c < nch; c++) {
        asm volatile("cp.async.wait_group 1;");
        __syncthreads();
        if (c + NSTG - 1 < nch) {
            uint32_t st = sb + ((c + NSTG - 1) % NSTG) * STGB;
            int k0 = (c + NSTG - 1) << 5;
            if (MODE == 0) {
                cpa_tile(st,              A0, lda, k0, tid);
                cpa_tile(st + TILE_B,     A1, lda, k0, tid);
                cpa_tile(st + 2 * TILE_B, B0, ldb, k0, tid);
                cpa_tile(st + 3 * TILE_B, B1, ldb, k0, tid);
            } else {
                cpa_tile(st,          A0, lda, k0, tid);
                cpa_tile(st + TILE_B, B0, ldb, k0, tid);
            }
        }
        asm volatile("cp.async.commit_group;");

        const uint32_t st = sb + (c % NSTG) * STGB;
#pragma unroll
        for (int k16 = 0; k16 < 2; k16++) {
            if (MODE == 1) {
                uint32_t fA[4][4], fB[4][4];
#pragma unroll
                for (int mt = 0; mt < 4; mt++)
                    ldmA(fA[mt], st, wm + mt * 16, k16, lane);
#pragma unroll
                for (int g = 0; g < 4; g++)
                    ldmB(fB[g], st + TILE_B, wn + g * 16, k16, lane);
#pragma unroll
                for (int mt = 0; mt < 4; mt++)
#pragma unroll
                    for (int nt = 0; nt < 8; nt++)
                        mmaH(acc[mt][nt], fA[mt], &fB[nt >> 1][(nt & 1) * 2]);
            } else {
                uint32_t fAh[4][4], fAl[4][4], fB[4][4];
#pragma unroll
                for (int mt = 0; mt < 4; mt++) {
                    ldmA(fAh[mt], st,          wm + mt * 16, k16, lane);
                    ldmA(fAl[mt], st + TILE_B, wm + mt * 16, k16, lane);
                }
#pragma unroll
                for (int g = 0; g < 4; g++)
                    ldmB(fB[g], st + 2 * TILE_B, wn + g * 16, k16, lane);
#pragma unroll
                for (int mt = 0; mt < 4; mt++)
#pragma unroll
                    for (int nt = 0; nt < 8; nt++)
                        mmaB(acc[mt][nt], fAh[mt], &fB[nt >> 1][(nt & 1) * 2]);
#pragma unroll
                for (int mt = 0; mt < 4; mt++)
#pragma unroll
                    for (int nt = 0; nt < 8; nt++)
                        mmaB(acc[mt][nt], fAl[mt], &fB[nt >> 1][(nt & 1) * 2]);
#pragma unroll
                for (int g = 0; g < 4; g++)
                    ldmB(fB[g], st + 3 * TILE_B, wn + g * 16, k16, lane);
#pragma unroll
                for (int mt = 0; mt < 4; mt++)
#pragma unroll
                    for (int nt = 0; nt < 8; nt++)
                        mmaB(acc[mt][nt], fAh[mt], &fB[nt >> 1][(nt & 1) * 2]);
            }
        }
        __syncthreads();
    }

    // epilogue
    const int rr = lane >> 2;
    const int cc2 = (lane & 3) * 2;
#pragma unroll
    for (int mt = 0; mt < 4; mt++) {
#pragma unroll
        for (int nt = 0; nt < 8; nt++) {
            int row0 = bm + wm + mt * 16 + rr;
            int col = bn + wn + nt * 8 + cc2;
            float cb0 = cBias ? cBias[col] : 0.f;
            float cb1 = cBias ? cBias[col + 1] : 0.f;
#pragma unroll
            for (int h = 0; h < 2; h++) {
                int row = row0 + h * 8;
                float rb = rBias ? rBias[row] : 0.f;
                float v0 = acc[mt][nt][h * 2 + 0] + rb + cb0;
                float v1 = acc[mt][nt][h * 2 + 1] + rb + cb1;
                long o = (long)bz * oS + (long)row * ldc + col;
                if (OUT == 0) {
                    *(float2*)(outF + o) = make_float2(v0, v1);
                } else if (OUT == 1) {
                    st_split2(oH + o, oL + o, v0, v1);
                } else {
                    __half* hp = reinterpret_cast<__half*>(oH);
                    *(half2*)(hp + o) = __floats2half2_rn(v0, v1);
                }
            }
        }
    }
}

// ---------------- elementwise kernels ----------------
__global__ void __launch_bounds__(256) split_w4(
    const float* __restrict__ w0, const float* __restrict__ w1,
    const float* __restrict__ w2, const float* __restrict__ w3,
    __half* __restrict__ gf,
    bf16* __restrict__ th, bf16* __restrict__ tl,
    bf16* __restrict__ ph, bf16* __restrict__ pl,
    __half* __restrict__ wf)
{
    const int seg = blockIdx.x >> 10;
    const int i = ((blockIdx.x & 1023) * 256 + threadIdx.x) * 2;
    if (seg == 0) {
        float2 v = *(const float2*)(w0 + i);
        *(half2*)(gf + i) = __floats2half2_rn(v.x, v.y);
    } else if (seg == 3) {
        float2 v = *(const float2*)(w3 + i);
        *(half2*)(wf + i) = __floats2half2_rn(v.x, v.y);
    } else {
        const float* w = seg == 1 ? w1 : w2;
        bf16* hi = seg == 1 ? th : ph;
        bf16* lo = seg == 1 ? tl : pl;
        float2 v = *(const float2*)(w + i);
        st_split2(hi + i, lo + i, v.x, v.y);
    }
}

__global__ void __launch_bounds__(256) xpose_split(const float* __restrict__ x,
                                                   bf16* __restrict__ hi, bf16* __restrict__ lo,
                                                   __half* __restrict__ xf)
{
    __shared__ float t[64][33];
    const int b = blockIdx.z, n0 = blockIdx.x * 32, c0 = blockIdx.y * 64;
    const int tx = threadIdx.x & 31, ty = threadIdx.x >> 5;
#pragma unroll
    for (int i = 0; i < 8; i++) {
        int r = ty + i * 8;
        t[r][tx] = x[((long)b * CC + c0 + r) * NT + n0 + tx];
    }
    __syncthreads();
#pragma unroll
    for (int i = 0; i < 4; i++) {
        int n = ty + i * 8;
        float v0 = t[tx * 2][n];
        float v1 = t[tx * 2 + 1][n];
        long o = ((long)b * NT + n0 + n) * CC + c0 + tx * 2;
        *(uint32_t*)(hi + o) = pack_bf(v0, v1);
        bf16 h0 = __float2bfloat16(v0), h1 = __float2bfloat16(v1);
        *(uint32_t*)(lo + o) = pack_bf(v0 - __bfloat162float(h0), v1 - __bfloat162float(h1));
        *(half2*)(xf + o) = __floats2half2_rn(v0, v1);
    }
}

__global__ void __launch_bounds__(256) softmax_h(const float* __restrict__ f,
                                                 __half* __restrict__ at)
{
    const float4* pv = (const float4*)(f + (size_t)blockIdx.x * NT);
    const int tid = threadIdx.x;
    float4 a = pv[tid], b = pv[tid + 256];
    float m = fmaxf(fmaxf(fmaxf(a.x, a.y), fmaxf(a.z, a.w)),
                    fmaxf(fmaxf(b.x, b.y), fmaxf(b.z, b.w)));
    __shared__ float red[8];
#pragma unroll
    for (int o = 16; o > 0; o >>= 1) m = fmaxf(m, __shfl_xor_sync(~0u, m, o));
    if ((tid & 31) == 0) red[tid >> 5] = m;
    __syncthreads();
    float mm = red[0];
#pragma unroll
    for (int i = 1; i < 8; i++) mm = fmaxf(mm, red[i]);
    __syncthreads();
    a.x = expf(a.x - mm); a.y = expf(a.y - mm); a.z = expf(a.z - mm); a.w = expf(a.w - mm);
    b.x = expf(b.x - mm); b.y = expf(b.y - mm); b.z = expf(b.z - mm); b.w = expf(b.w - mm);
    float s = (a.x + a.y) + (a.z + a.w) + (b.x + b.y) + (b.z + b.w);
#pragma unroll
    for (int o = 16; o > 0; o >>= 1) s += __shfl_xor_sync(~0u, s, o);
    if ((tid & 31) == 0) red[tid >> 5] = s;
    __syncthreads();
    float sum = 0.f;
#pragma unroll
    for (int i = 0; i < 8; i++) sum += red[i];
    float inv = 1.0f / sum;
    size_t off = (size_t)blockIdx.x * NT;
    uint2 pa = make_uint2(h2_u32(__floats2half2_rn(a.x * inv, a.y * inv)),
                          h2_u32(__floats2half2_rn(a.z * inv, a.w * inv)));
    *(uint2*)(at + off + tid * 4) = pa;
    uint2 pb = make_uint2(h2_u32(__floats2half2_rn(b.x * inv, b.y * inv)),
                          h2_u32(__floats2half2_rn(b.z * inv, b.w * inv)));
    *(uint2*)(at + off + 1024 + tid * 4) = pb;
}

// BN + residual; wy is fp16 now. Each thread owns 4 half2 per batch (8 values).
__global__ void __launch_bounds__(256)
bn_residual(const __half* __restrict__ wy, const float* __restrict__ x,
            const float* __restrict__ gamma, const float* __restrict__ beta,
            float* __restrict__ out)
{
    const int c = blockIdx.x, tid = threadIdx.x;
    float2 vals[16];
    float s = 0.f, ss = 0.f;
#pragma unroll
    for (int b = 0; b < BB; b++) {
        const __half* p = wy + ((size_t)b * CC + c) * NT;
#pragma unroll
        for (int j = 0; j < 4; j++) {
            half2 h = *(const half2*)(p + (tid + j * 256) * 2);
            float2 v = __half22float2(h);
            vals[b * 4 + j] = v;
            s += v.x + v.y;
            ss += v.x * v.x + v.y * v.y;
        }
    }
    __shared__ float r1[8], r2[8];
#pragma unroll
    for (int o = 16; o > 0; o >>= 1) {
        s += __shfl_xor_sync(~0u, s, o);
        ss += __shfl_xor_sync(~0u, ss, o);
    }
    if ((tid & 31) == 0) { r1[tid >> 5] = s; r2[tid >> 5] = ss; }
    __syncthreads();
    s = 0.f; ss = 0.f;
#pragma unroll
    for (int i = 0; i < 8; i++) { s += r1[i]; ss += r2[i]; }
    const float cnt = (float)(BB * NT);
    float mean = s / cnt;
    float var = ss / cnt - mean * mean;
    float scale = rsqrtf(var + 1e-5f) * gamma[c];
    float shift = beta[c] - mean * scale;
#pragma unroll
    for (int b = 0; b < BB; b++) {
        size_t off = ((size_t)b * CC + c) * NT;
#pragma unroll
        for (int j = 0; j < 4; j++) {
            int n = (tid + j * 256) * 2;
            float2 xv = *(const float2*)(x + off + n);
            float2 v = vals[b * 4 + j];
            float2 w;
            w.x = v.x * scale + shift + xv.x;
            w.y = v.y * scale + shift + xv.y;
            *(float2*)(out + off + n) = w;
        }
    }
}

// ---------------------------------------------------------------------------
extern "C" void kernel_launch(void* const* d_in, const int* in_sizes, int n_in,
                              void* d_out, int out_size)
{
    const float* x   = (const float*)d_in[0];
    const float* gw  = (const float*)d_in[1];
    const float* gb  = (const float*)d_in[2];
    const float* tw  = (const float*)d_in[3];
    const float* tb  = (const float*)d_in[4];
    const float* pw  = (const float*)d_in[5];
    const float* pb  = (const float*)d_in[6];
    const float* ww  = (const float*)d_in[7];
    const float* wb  = (const float*)d_in[8];
    const float* bg  = (const float*)d_in[9];
    const float* bbt = (const float*)d_in[10];
    float* out = (float*)d_out;

    bf16 *xTh, *xTl, *wth, *wtl, *wph, *wpl, *thh, *thl, *phh, *phl;
    __half *xTf, *wgf, *wwf, *gs, *at, *yv, *wyh;
    float *ff;
    cudaGetSymbolAddress((void**)&xTh, s_xT_h); cudaGetSymbolAddress((void**)&xTl, s_xT_l);
    cudaGetSymbolAddress((void**)&xTf, s_xT_f);
    cudaGetSymbolAddress((void**)&wth, s_wt_h); cudaGetSymbolAddress((void**)&wtl, s_wt_l);
    cudaGetSymbolAddress((void**)&wph, s_wp_h); cudaGetSymbolAddress((void**)&wpl, s_wp_l);
    cudaGetSymbolAddress((void**)&wgf, s_wgF);  cudaGetSymbolAddress((void**)&wwf, s_wwF);
    cudaGetSymbolAddress((void**)&thh, s_th_h); cudaGetSymbolAddress((void**)&thl, s_th_l);
    cudaGetSymbolAddress((void**)&phh, s_ph_h); cudaGetSymbolAddress((void**)&phl, s_ph_l);
    cudaGetSymbolAddress((void**)&gs,  s_gs);   cudaGetSymbolAddress((void**)&at,  s_at);
    cudaGetSymbolAddress((void**)&yv,  s_y);    cudaGetSymbolAddress((void**)&wyh, s_wyh);
    cudaGetSymbolAddress((void**)&ff,  s_f);

    cudaFuncSetAttribute(gemm_tc<1, 0>, cudaFuncAttributeMaxDynamicSharedMemorySize, SMEM_BF);
    cudaFuncSetAttribute(gemm_tc<0, 0>, cudaFuncAttributeMaxDynamicSharedMemorySize, SMEM_BF);
    cudaFuncSetAttribute(gemm_tc<2, 1>, cudaFuncAttributeMaxDynamicSharedMemorySize, SMEM_H1);

    split_w4<<<4 * 1024, 256>>>(gw, tw, pw, ww, wgf, wth, wtl, wph, wpl, wwf);
    xpose_split<<<dim3(NT / 32, CC / 64, BB), 256>>>(x, xTh, xTl, xTf);

    const long sXT = (long)NT * CC, sPR = (long)NT * CIN;
    const long sGS = (long)CIN * NT, sAT = (long)NT * NT, sWY = (long)CC * NT;

    // theta + phi fused (bf16 3-prod): rows=NT cols=CIN K=CC, z in [0,8)
    gemm_tc<1, 0><<<dim3(CIN / 128, NT / 128, 2 * BB), 128, SMEM_BF>>>(
        xTh, xTl, sXT, CC, wth, wtl, 0, CC, nullptr, thh, thl, sPR, CIN, nullptr, tb, CC,
        wph, wpl, pb, phh, phl);
    // g (fp16 1-prod): rows=CIN (o), cols=NT (m), K=CC; out fp16 [o,m] + g_b
    gemm_tc<2, 1><<<dim3(NT / 128, CIN / 128, BB), 128, SMEM_H1>>>(
        (const bf16*)wgf, nullptr, 0, CC, (const bf16*)xTf, nullptr, sXT, CC,
        nullptr, (bf16*)gs, nullptr, sGS, NT, gb, nullptr, CC,
        nullptr, nullptr, nullptr, nullptr, nullptr);
    // f (bf16 3-prod): rows=NT cols=NT K=CIN, out fp32
    gemm_tc<0, 0><<<dim3(NT / 128, NT / 128, BB), 128, SMEM_BF>>>(
        thh, thl, sPR, CIN, phh, phl, sPR, CIN, ff, nullptr, nullptr, sAT, NT, nullptr, nullptr, CIN,
        nullptr, nullptr, nullptr, nullptr, nullptr);
    // softmax -> single fp16 attn
    softmax_h<<<BB * NT, 256>>>(ff, at);
    // y (fp16 1-prod): rows=NT (n), cols=CIN (o), K=NT; out fp16 [n,o]
    gemm_tc<2, 1><<<dim3(CIN / 128, NT / 128, BB), 128, SMEM_H1>>>(
        (const bf16*)at, nullptr, sAT, NT, (const bf16*)gs, nullptr, sGS, NT,
        nullptr, (bf16*)yv, nullptr, sPR, CIN, nullptr, nullptr, NT,
        nullptr, nullptr, nullptr, nullptr, nullptr);
    // w_y (fp16 1-prod): rows=CC (c), cols=NT (n), K=CIN; out fp16 + wb
    gemm_tc<2, 1><<<dim3(NT / 128, CC / 128, BB), 128, SMEM_H1>>>(
        (const bf16*)wwf, nullptr, 0, CIN, (const bf16*)yv, nullptr, sPR, CIN,
        nullptr, (bf16*)wyh, nullptr, sWY, NT, wb, nullptr, CIN,
        nullptr, nullptr, nullptr, nullptr, nullptr);
    // BN + residual (reads fp16 wy)
    bn_residual<<<CC, 256>>>(wyh, x, bg, bbt, out);
}

// round 16
// speedup vs baseline: 1.6630x; 1.0357x over previous
#include <cuda_runtime.h>
#include <cuda_bf16.h>
#include <cuda_fp16.h>
#include <cstdint>

typedef __nv_bfloat16 bf16;

#define BB 4
#define CC 1024
#define CIN 512
#define NT 2048

// ---------------- static scratch ----------------
__device__ __align__(256) bf16 s_xT_h[BB * NT * CC];
__device__ __align__(256) bf16 s_xT_l[BB * NT * CC];
__device__ __align__(256) bf16 s_wt_h[CIN * CC], s_wt_l[CIN * CC];
__device__ __align__(256) bf16 s_wp_h[CIN * CC], s_wp_l[CIN * CC];
__device__ __align__(256) bf16 s_th_h[BB * NT * CIN], s_th_l[BB * NT * CIN];
__device__ __align__(256) bf16 s_ph_h[BB * NT * CIN], s_ph_l[BB * NT * CIN];
__device__ __align__(256) float s_f[BB * NT * NT];
__device__ __align__(256) __half s_xT_f[BB * NT * CC];
__device__ __align__(256) __half s_wgF[CIN * CC];
__device__ __align__(256) __half s_wwF[CC * CIN];
__device__ __align__(256) __half s_gs[BB * CIN * NT];
__device__ __align__(256) __half s_at[BB * NT * NT];
__device__ __align__(256) __half s_y[BB * NT * CIN];
__device__ __align__(256) __half s_wyh[BB * CC * NT];

// ---------------- helpers ----------------
__device__ __forceinline__ uint32_t smem_u32(const void* p) {
    uint32_t a;
    asm("{ .reg .u64 t; cvta.to.shared.u64 t, %1; cvt.u32.u64 %0, t; }" : "=r"(a) : "l"(p));
    return a;
}
__device__ __forceinline__ void st_split2(bf16* hi, bf16* lo, float v0, float v1) {
    bf16 h0 = __float2bfloat16(v0), h1 = __float2bfloat16(v1);
    *(uint32_t*)hi = (uint32_t)__bfloat16_as_ushort(h0) |
                     ((uint32_t)__bfloat16_as_ushort(h1) << 16);
    bf16 l0 = __float2bfloat16(v0 - __bfloat162float(h0));
    bf16 l1 = __float2bfloat16(v1 - __bfloat162float(h1));
    *(uint32_t*)lo = (uint32_t)__bfloat16_as_ushort(l0) |
                     ((uint32_t)__bfloat16_as_ushort(l1) << 16);
}
__device__ __forceinline__ uint32_t pack_bf(float v0, float v1) {
    return (uint32_t)__bfloat16_as_ushort(__float2bfloat16(v0)) |
           ((uint32_t)__bfloat16_as_ushort(__float2bfloat16(v1)) << 16);
}
__device__ __forceinline__ uint32_t h2_u32(half2 h) {
    uint32_t u;
    *(half2*)&u = h;
    return u;
}

// ---------------- HMMA GEMM ----------------
// MODE 0: bf16, A/B 2-limb, 3 products (HH+LH+HL)
// MODE 1: fp16, single-limb, 1 product
// CTA 128x128, 4 warps (2x2) of 64x64, K-chunk 32, 3-stage cp.async, 2 CTA/SM.
#define NSTG 3
#define TILE_B 8192
#define SMEM_BF (NSTG * 4 * TILE_B)   // 96 KB
#define SMEM_H1 (NSTG * 2 * TILE_B)   // 48 KB

__device__ __forceinline__ uint32_t sw(int row, int kv) {
    return (uint32_t)(row * 64 + ((kv ^ ((row >> 1) & 3)) << 4));
}
__device__ __forceinline__ void cpa_tile(uint32_t sdst, const bf16* __restrict__ g,
                                         int ld, int k0, int tid) {
#pragma unroll
    for (int i = 0; i < 4; i++) {
        int idx = tid + i * 128;
        int row = idx >> 2;
        int kv  = idx & 3;
        uint32_t dst = sdst + sw(row, kv);
        const void* src = g + (long)row * ld + k0 + kv * 8;
        asm volatile("cp.async.cg.shared.global [%0], [%1], 16;" :: "r"(dst), "l"(src));
    }
}
__device__ __forceinline__ void ldmA(uint32_t* r, uint32_t base, int m0, int k16, int lane) {
    int m = m0 + (lane & 15);
    int kv = k16 * 2 + (lane >> 4);
    uint32_t addr = base + sw(m, kv);
    asm volatile("ldmatrix.sync.aligned.m8n8.x4.shared.b16 {%0,%1,%2,%3}, [%4];"
                 : "=r"(r[0]), "=r"(r[1]), "=r"(r[2]), "=r"(r[3]) : "r"(addr));
}
__device__ __forceinline__ void ldmB(uint32_t* r, uint32_t base, int n0, int k16, int lane) {
    int row = n0 + (lane & 7) + ((lane >> 4) << 3);
    int kv = k16 * 2 + ((lane >> 3) & 1);
    uint32_t addr = base + sw(row, kv);
    asm volatile("ldmatrix.sync.aligned.m8n8.x4.shared.b16 {%0,%1,%2,%3}, [%4];"
                 : "=r"(r[0]), "=r"(r[1]), "=r"(r[2]), "=r"(r[3]) : "r"(addr));
}
__device__ __forceinline__ void mmaB(float* c, const uint32_t* a, const uint32_t* b) {
    asm volatile(
        "mma.sync.aligned.m16n8k16.row.col.f32.bf16.bf16.f32 "
        "{%0,%1,%2,%3},{%4,%5,%6,%7},{%8,%9},{%0,%1,%2,%3};"
        : "+f"(c[0]), "+f"(c[1]), "+f"(c[2]), "+f"(c[3])
        : "r"(a[0]), "r"(a[1]), "r"(a[2]), "r"(a[3]), "r"(b[0]), "r"(b[1]));
}
__device__ __forceinline__ void mmaH(float* c, const uint32_t* a, const uint32_t* b) {
    asm volatile(
        "mma.sync.aligned.m16n8k16.row.col.f32.f16.f16.f32 "
        "{%0,%1,%2,%3},{%4,%5,%6,%7},{%8,%9},{%0,%1,%2,%3};"
        : "+f"(c[0]), "+f"(c[1]), "+f"(c[2]), "+f"(c[3])
        : "r"(a[0]), "r"(a[1]), "r"(a[2]), "r"(a[3]), "r"(b[0]), "r"(b[1]));
}

// OUT: 0 = fp32 (+rBias,+cBias), 1 = split bf16 (+biases), 2 = single fp16 (+rBias)
template <int OUT, int MODE>
__device__ __forceinline__ void gemm_body(
    const bf16* __restrict__ aH, const bf16* __restrict__ aL, long aS, int lda,
    const bf16* __restrict__ bH, const bf16* __restrict__ bL, long bS, int ldb,
    float* __restrict__ outF, bf16* __restrict__ oH, bf16* __restrict__ oL,
    long oS, int ldc, const float* __restrict__ rBias,
    const float* __restrict__ cBias, int K,
    int bn, int bm, int bz, char* smraw)
{
    constexpr int NTL = (MODE == 0) ? 4 : 2;
    constexpr int STGB = NTL * TILE_B;
    const uint32_t sb = smem_u32(smraw);

    const int tid = threadIdx.x, wid = tid >> 5, lane = tid & 31;
    const int wm = (wid & 1) * 64;
    const int wn = (wid >> 1) * 64;

    const bf16* A0 = aH + (long)bz * aS + (long)bm * lda;
    const bf16* A1 = (MODE == 0) ? aL + (long)bz * aS + (long)bm * lda : nullptr;
    const bf16* B0 = bH + (long)bz * bS + (long)bn * ldb;
    const bf16* B1 = (MODE == 0) ? bL + (long)bz * bS + (long)bn * ldb : nullptr;
    const int nch = K >> 5;

    float acc[4][8][4];
#pragma unroll
    for (int i = 0; i < 4; i++)
#pragma unroll
        for (int j = 0; j < 8; j++)
#pragma unroll
            for (int e = 0; e < 4; e++) acc[i][j][e] = 0.f;

#pragma unroll
    for (int s = 0; s < NSTG - 1; s++) {
        uint32_t st = sb + s * STGB;
        int k0 = s << 5;
        if (MODE == 0) {
            cpa_tile(st,              A0, lda, k0, tid);
            cpa_tile(st + TILE_B,     A1, lda, k0, tid);
            cpa_tile(st + 2 * TILE_B, B0, ldb, k0, tid);
            cpa_tile(st + 3 * TILE_B, B1, ldb, k0, tid);
        } else {
            cpa_tile(st,          A0, lda, k0, tid);
            cpa_tile(st + TILE_B, B0, ldb, k0, tid);
        }
        asm volatile("cp.async.commit_group;");
    }

    for (int c = 0; c < nch; c++) {
        asm volatile("cp.async.wait_group 1;");
        __syncthreads();
        if (c + NSTG - 1 < nch) {
            uint32_t st = sb + ((c + NSTG - 1) % NSTG) * STGB;
            int k0 = (c + NSTG - 1) << 5;
            if (MODE == 0) {
                cpa_tile(st,              A0, lda, k0, tid);
                cpa_tile(st + TILE_B,     A1, lda, k0, tid);
                cpa_tile(st + 2 * TILE_B, B0, ldb, k0, tid);
                cpa_tile(st + 3 * TILE_B, B1, ldb, k0, tid);
            } else {
                cpa_tile(st,          A0, lda, k0, tid);
                cpa_tile(st + TILE_B, B0, ldb, k0, tid);
            }
        }
        asm volatile("cp.async.commit_group;");

        const uint32_t st = sb + (c % NSTG) * STGB;
#pragma unroll
        for (int k16 = 0; k16 < 2; k16++) {
            if (MODE == 1) {
                uint32_t fA[4][4], fB[4][4];
#pragma unroll
                for (int mt = 0; mt < 4; mt++)
                    ldmA(fA[mt], st, wm + mt * 16, k16, lane);
#pragma unroll
                for (int g = 0; g < 4; g++)
                    ldmB(fB[g], st + TILE_B, wn + g * 16, k16, lane);
#pragma unroll
                for (int mt = 0; mt < 4; mt++)
#pragma unroll
                    for (int nt = 0; nt < 8; nt++)
                        mmaH(acc[mt][nt], fA[mt], &fB[nt >> 1][(nt & 1) * 2]);
            } else {
                uint32_t fAh[4][4], fAl[4][4], fB[4][4];
#pragma unroll
                for (int mt = 0; mt < 4; mt++) {
                    ldmA(fAh[mt], st,          wm + mt * 16, k16, lane);
                    ldmA(fAl[mt], st + TILE_B, wm + mt * 16, k16, lane);
                }
#pragma unroll
                for (int g = 0; g < 4; g++)
                    ldmB(fB[g], st + 2 * TILE_B, wn + g * 16, k16, lane);
#pragma unroll
                for (int mt = 0; mt < 4; mt++)
#pragma unroll
                    for (int nt = 0; nt < 8; nt++)
                        mmaB(acc[mt][nt], fAh[mt], &fB[nt >> 1][(nt & 1) * 2]);
#pragma unroll
                for (int mt = 0; mt < 4; mt++)
#pragma unroll
                    for (int nt = 0; nt < 8; nt++)
                        mmaB(acc[mt][nt], fAl[mt], &fB[nt >> 1][(nt & 1) * 2]);
#pragma unroll
                for (int g = 0; g < 4; g++)
                    ldmB(fB[g], st + 3 * TILE_B, wn + g * 16, k16, lane);
#pragma unroll
                for (int mt = 0; mt < 4; mt++)
#pragma unroll
                    for (int nt = 0; nt < 8; nt++)
                        mmaB(acc[mt][nt], fAh[mt], &fB[nt >> 1][(nt & 1) * 2]);
            }
        }
        __syncthreads();
    }

    const int rr = lane >> 2;
    const int cc2 = (lane & 3) * 2;
#pragma unroll
    for (int mt = 0; mt < 4; mt++) {
#pragma unroll
        for (int nt = 0; nt < 8; nt++) {
            int row0 = bm + wm + mt * 16 + rr;
            int col = bn + wn + nt * 8 + cc2;
            float cb0 = cBias ? cBias[col] : 0.f;
            float cb1 = cBias ? cBias[col + 1] : 0.f;
#pragma unroll
            for (int h = 0; h < 2; h++) {
                int row = row0 + h * 8;
                float rb = rBias ? rBias[row] : 0.f;
                float v0 = acc[mt][nt][h * 2 + 0] + rb + cb0;
                float v1 = acc[mt][nt][h * 2 + 1] + rb + cb1;
                long o = (long)bz * oS + (long)row * ldc + col;
                if (OUT == 0) {
                    *(float2*)(outF + o) = make_float2(v0, v1);
                } else if (OUT == 1) {
                    st_split2(oH + o, oL + o, v0, v1);
                } else {
                    __half* hp = reinterpret_cast<__half*>(oH);
                    *(half2*)(hp + o) = __floats2half2_rn(v0, v1);
                }
            }
        }
    }
}

// standalone GEMM kernel (f, y, wy)
template <int OUT, int MODE>
__global__ void __launch_bounds__(128, 2)
gemm_tc(const bf16* __restrict__ aH, const bf16* __restrict__ aL, long aS, int lda,
        const bf16* __restrict__ bH, const bf16* __restrict__ bL, long bS, int ldb,
        float* __restrict__ outF, bf16* __restrict__ oH, bf16* __restrict__ oL,
        long oS, int ldc, const float* __restrict__ rBias,
        const float* __restrict__ cBias, int K)
{
    extern __shared__ char smraw[];
    gemm_body<OUT, MODE>(aH, aL, aS, lda, bH, bL, bS, ldb, outF, oH, oL, oS, ldc,
                         rBias, cBias, K,
                         blockIdx.x * 128, blockIdx.y * 128, blockIdx.z, smraw);
}

// fused theta/phi (MODE0, z in [0,8)) + g (MODE1, z in [8,12)); grid (64,1,12)
__global__ void __launch_bounds__(128, 2)
proj_fused(const bf16* __restrict__ xTh, const bf16* __restrict__ xTl,
           const bf16* __restrict__ wth, const bf16* __restrict__ wtl,
           const bf16* __restrict__ wph, const bf16* __restrict__ wpl,
           bf16* __restrict__ thh, bf16* __restrict__ thl,
           bf16* __restrict__ phh, bf16* __restrict__ phl,
           const float* __restrict__ tb, const float* __restrict__ pb,
           const __half* __restrict__ wgf, const __half* __restrict__ xTf,
           __half* __restrict__ gs, const float* __restrict__ gb)
{
    extern __shared__ char smraw[];
    const long sXT = (long)NT * CC, sPR = (long)NT * CIN, sGS = (long)CIN * NT;
    const int z = blockIdx.z;
    if (z < 2 * BB) {
        const int bz = z & (BB - 1);
        const bool isPhi = z >= BB;
        const int bn = (blockIdx.x & 3) * 128;     // CIN cols
        const int bm = (blockIdx.x >> 2) * 128;    // NT rows
        gemm_body<1, 0>(xTh, xTl, sXT, CC,
                        isPhi ? wph : wth, isPhi ? wpl : wtl, 0, CC,
                        nullptr, isPhi ? phh : thh, isPhi ? phl : thl, sPR, CIN,
                        nullptr, isPhi ? pb : tb, CC, bn, bm, bz, smraw);
    } else {
        const int bz = z - 2 * BB;
        const int bn = (blockIdx.x & 15) * 128;    // NT cols
        const int bm = (blockIdx.x >> 4) * 128;    // CIN rows
        gemm_body<2, 1>((const bf16*)wgf, nullptr, 0, CC,
                        (const bf16*)xTf, nullptr, sXT, CC,
                        nullptr, (bf16*)gs, nullptr, sGS, NT,
                        gb, nullptr, CC, bn, bm, bz, smraw);
    }
}

// ---------------- fused prep: weight splits (blocks 0..4095) + x transpose (4096..8191)
__global__ void __launch_bounds__(256) prep(
    const float* __restrict__ x,
    const float* __restrict__ w0, const float* __restrict__ w1,
    const float* __restrict__ w2, const float* __restrict__ w3,
    __half* __restrict__ gf,
    bf16* __restrict__ th, bf16* __restrict__ tl,
    bf16* __restrict__ ph, bf16* __restrict__ pl,
    __half* __restrict__ wf,
    bf16* __restrict__ xhi, bf16* __restrict__ xlo, __half* __restrict__ xf)
{
    __shared__ float t[64][33];
    if (blockIdx.x < 4096) {
        const int seg = blockIdx.x >> 10;
        const int i = ((blockIdx.x & 1023) * 256 + threadIdx.x) * 2;
        if (seg == 0) {
            float2 v = *(const float2*)(w0 + i);
            *(half2*)(gf + i) = __floats2half2_rn(v.x, v.y);
        } else if (seg == 3) {
            float2 v = *(const float2*)(w3 + i);
            *(half2*)(wf + i) = __floats2half2_rn(v.x, v.y);
        } else {
            const float* w = seg == 1 ? w1 : w2;
            bf16* hi = seg == 1 ? th : ph;
            bf16* lo = seg == 1 ? tl : pl;
            float2 v = *(const float2*)(w + i);
            st_split2(hi + i, lo + i, v.x, v.y);
        }
        return;
    }
    const int idx = blockIdx.x - 4096;
    const int b = idx >> 10;
    const int rem = idx & 1023;
    const int n0 = (rem & 63) * 32;
    const int c0 = (rem >> 6) * 64;
    const int tx = threadIdx.x & 31, ty = threadIdx.x >> 5;
#pragma unroll
    for (int i = 0; i < 8; i++) {
        int r = ty + i * 8;
        t[r][tx] = x[((long)b * CC + c0 + r) * NT + n0 + tx];
    }
    __syncthreads();
#pragma unroll
    for (int i = 0; i < 4; i++) {
        int n = ty + i * 8;
        float v0 = t[tx * 2][n];
        float v1 = t[tx * 2 + 1][n];
        long o = ((long)b * NT + n0 + n) * CC + c0 + tx * 2;
        *(uint32_t*)(xhi + o) = pack_bf(v0, v1);
        bf16 h0 = __float2bfloat16(v0), h1 = __float2bfloat16(v1);
        *(uint32_t*)(xlo + o) = pack_bf(v0 - __bfloat162float(h0), v1 - __bfloat162float(h1));
        *(half2*)(xf + o) = __floats2half2_rn(v0, v1);
    }
}

__global__ void __launch_bounds__(256) softmax_h(const float* __restrict__ f,
                                                 __half* __restrict__ at)
{
    const float4* pv = (const float4*)(f + (size_t)blockIdx.x * NT);
    const int tid = threadIdx.x;
    float4 a = pv[tid], b = pv[tid + 256];
    float m = fmaxf(fmaxf(fmaxf(a.x, a.y), fmaxf(a.z, a.w)),
                    fmaxf(fmaxf(b.x, b.y), fmaxf(b.z, b.w)));
    __shared__ float red[8];
#pragma unroll
    for (int o = 16; o > 0; o >>= 1) m = fmaxf(m, __shfl_xor_sync(~0u, m, o));
    if ((tid & 31) == 0) red[tid >> 5] = m;
    __syncthreads();
    float mm = red[0];
#pragma unroll
    for (int i = 1; i < 8; i++) mm = fmaxf(mm, red[i]);
    __syncthreads();
    a.x = expf(a.x - mm); a.y = expf(a.y - mm); a.z = expf(a.z - mm); a.w = expf(a.w - mm);
    b.x = expf(b.x - mm); b.y = expf(b.y - mm); b.z = expf(b.z - mm); b.w = expf(b.w - mm);
    float s = (a.x + a.y) + (a.z + a.w) + (b.x + b.y) + (b.z + b.w);
#pragma unroll
    for (int o = 16; o > 0; o >>= 1) s += __shfl_xor_sync(~0u, s, o);
    if ((tid & 31) == 0) red[tid >> 5] = s;
    __syncthreads();
    float sum = 0.f;
#pragma unroll
    for (int i = 0; i < 8; i++) sum += red[i];
    float inv = 1.0f / sum;
    size_t off = (size_t)blockIdx.x * NT;
    uint2 pa = make_uint2(h2_u32(__floats2half2_rn(a.x * inv, a.y * inv)),
                          h2_u32(__floats2half2_rn(a.z * inv, a.w * inv)));
    *(uint2*)(at + off + tid * 4) = pa;
    uint2 pb = make_uint2(h2_u32(__floats2half2_rn(b.x * inv, b.y * inv)),
                          h2_u32(__floats2half2_rn(b.z * inv, b.w * inv)));
    *(uint2*)(at + off + 1024 + tid * 4) = pb;
}

__global__ void __launch_bounds__(256)
bn_residual(const __half* __restrict__ wy, const float* __restrict__ x,
            const float* __restrict__ gamma, const float* __restrict__ beta,
            float* __restrict__ out)
{
    const int c = blockIdx.x, tid = threadIdx.x;
    float2 vals[16];
    float s = 0.f, ss = 0.f;
#pragma unroll
    for (int b = 0; b < BB; b++) {
        const __half* p = wy + ((size_t)b * CC + c) * NT;
#pragma unroll
        for (int j = 0; j < 4; j++) {
            half2 h = *(const half2*)(p + (tid + j * 256) * 2);
            float2 v = __half22float2(h);
            vals[b * 4 + j] = v;
            s += v.x + v.y;
            ss += v.x * v.x + v.y * v.y;
        }
    }
    __shared__ float r1[8], r2[8];
#pragma unroll
    for (int o = 16; o > 0; o >>= 1) {
        s += __shfl_xor_sync(~0u, s, o);
        ss += __shfl_xor_sync(~0u, ss, o);
    }
    if ((tid & 31) == 0) { r1[tid >> 5] = s; r2[tid >> 5] = ss; }
    __syncthreads();
    s = 0.f; ss = 0.f;
#pragma unroll
    for (int i = 0; i < 8; i++) { s += r1[i]; ss += r2[i]; }
    const float cnt = (float)(BB * NT);
    float mean = s / cnt;
    float var = ss / cnt - mean * mean;
    float scale = rsqrtf(var + 1e-5f) * gamma[c];
    float shift = beta[c] - mean * scale;
#pragma unroll
    for (int b = 0; b < BB; b++) {
        size_t off = ((size_t)b * CC + c) * NT;
#pragma unroll
        for (int j = 0; j < 4; j++) {
            int n = (tid + j * 256) * 2;
            float2 xv = *(const float2*)(x + off + n);
            float2 v = vals[b * 4 + j];
            float2 w;
            w.x = v.x * scale + shift + xv.x;
            w.y = v.y * scale + shift + xv.y;
            *(float2*)(out + off + n) = w;
        }
    }
}

// ---------------------------------------------------------------------------
extern "C" void kernel_launch(void* const* d_in, const int* in_sizes, int n_in,
                              void* d_out, int out_size)
{
    const float* x   = (const float*)d_in[0];
    const float* gw  = (const float*)d_in[1];
    const float* gb  = (const float*)d_in[2];
    const float* tw  = (const float*)d_in[3];
    const float* tb  = (const float*)d_in[4];
    const float* pw  = (const float*)d_in[5];
    const float* pb  = (const float*)d_in[6];
    const float* ww  = (const float*)d_in[7];
    const float* wb  = (const float*)d_in[8];
    const float* bg  = (const float*)d_in[9];
    const float* bbt = (const float*)d_in[10];
    float* out = (float*)d_out;

    bf16 *xTh, *xTl, *wth, *wtl, *wph, *wpl, *thh, *thl, *phh, *phl;
    __half *xTf, *wgf, *wwf, *gs, *at, *yv, *wyh;
    float *ff;
    cudaGetSymbolAddress((void**)&xTh, s_xT_h); cudaGetSymbolAddress((void**)&xTl, s_xT_l);
    cudaGetSymbolAddress((void**)&xTf, s_xT_f);
    cudaGetSymbolAddress((void**)&wth, s_wt_h); cudaGetSymbolAddress((void**)&wtl, s_wt_l);
    cudaGetSymbolAddress((void**)&wph, s_wp_h); cudaGetSymbolAddress((void**)&wpl, s_wp_l);
    cudaGetSymbolAddress((void**)&wgf, s_wgF);  cudaGetSymbolAddress((void**)&wwf, s_wwF);
    cudaGetSymbolAddress((void**)&thh, s_th_h); cudaGetSymbolAddress((void**)&thl, s_th_l);
    cudaGetSymbolAddress((void**)&phh, s_ph_h); cudaGetSymbolAddress((void**)&phl, s_ph_l);
    cudaGetSymbolAddress((void**)&gs,  s_gs);   cudaGetSymbolAddress((void**)&at,  s_at);
    cudaGetSymbolAddress((void**)&yv,  s_y);    cudaGetSymbolAddress((void**)&wyh, s_wyh);
    cudaGetSymbolAddress((void**)&ff,  s_f);

    cudaFuncSetAttribute(proj_fused,    cudaFuncAttributeMaxDynamicSharedMemorySize, SMEM_BF);
    cudaFuncSetAttribute(gemm_tc<0, 0>, cudaFuncAttributeMaxDynamicSharedMemorySize, SMEM_BF);
    cudaFuncSetAttribute(gemm_tc<2, 1>, cudaFuncAttributeMaxDynamicSharedMemorySize, SMEM_H1);

    // fused weight split + x transpose
    prep<<<8192, 256>>>(x, gw, tw, pw, ww, wgf, wth, wtl, wph, wpl, wwf, xTh, xTl, xTf);

    const long sXT = (long)NT * CC, sPR = (long)NT * CIN;
    const long sGS = (long)CIN * NT, sAT = (long)NT * NT, sWY = (long)CC * NT;

    // theta + phi (bf16 3-prod) + g (fp16 1-prod) in one launch
    proj_fused<<<dim3(64, 1, 3 * BB), 128, SMEM_BF>>>(
        xTh, xTl, wth, wtl, wph, wpl, thh, thl, phh, phl, tb, pb, wgf, xTf, gs, gb);
    // f (bf16 3-prod): rows=NT cols=NT K=CIN, out fp32
    gemm_tc<0, 0><<<dim3(NT / 128, NT / 128, BB), 128, SMEM_BF>>>(
        thh, thl, sPR, CIN, phh, phl, sPR, CIN, ff, nullptr, nullptr, sAT, NT,
        nullptr, nullptr, CIN);
    // softmax -> single fp16 attn
    softmax_h<<<BB * NT, 256>>>(ff, at);
    // y (fp16 1-prod): rows=NT (n), cols=CIN (o), K=NT; out fp16 [n,o]
    gemm_tc<2, 1><<<dim3(CIN / 128, NT / 128, BB), 128, SMEM_H1>>>(
        (const bf16*)at, nullptr, sAT, NT, (const bf16*)gs, nullptr, sGS, NT,
        nullptr, (bf16*)yv, nullptr, sPR, CIN, nullptr, nullptr, NT);
    // w_y (fp16 1-prod): rows=CC (c), cols=NT (n), K=CIN; out fp16 + wb
    gemm_tc<2, 1><<<dim3(NT / 128, CC / 128, BB), 128, SMEM_H1>>>(
        (const bf16*)wwf, nullptr, 0, CIN, (const bf16*)yv, nullptr, sPR, CIN,
        nullptr, (bf16*)wyh, nullptr, sWY, NT, wb, nullptr, CIN);
    // BN + residual (reads fp16 wy)
    bn_residual<<<CC, 256>>>(wyh, x, bg, bbt, out);
}